// round 11
// baseline (speedup 1.0000x reference)
#include <cuda_runtime.h>
#include <cuda_fp16.h>
#include <cstdint>
#include <math.h>

#define NC 2048
#define DH 1024
#define DO 512
#define GIN 1537
#define LDT 1600           // GRU K padded to multiple of 64
#define KENG 2048

// ---------------- scratch ----------------
__device__ __half g_eA[NC * KENG];                        // engine A (single fp16)
__device__ __half g_eB[2][DO * KENG];                     // engine B^T re/im (single fp16)
__device__ __half g_WT[4][DH * LDT];                      // GRU weights^T (single fp16)
__device__ __half g_cm[NC * LDT];                         // GRU gate input
__device__ __half g_cr[NC * LDT];                         // candidate re input
__device__ __half g_ci[NC * LDT];                         // candidate im input
__device__ float g_vre[DO];
__device__ float g_vim[DO];
__device__ float g_ore[NC * DO];
__device__ float g_oim[NC * DO];
__device__ float g_t[NC];                 // raw sum of squares (atomicAdd target)
__device__ float g_stats[2];
__device__ float g_z[NC * DH];
__device__ float g_rr[NC * DH];
__device__ float g_nre[NC * DH];
__device__ float g_nim[NC * DH];
__device__ float g_fmp[128 * DH];         // fmean partials
__device__ float g_fm[2 * 8 * DH];
__device__ float g_gm[2 * DH];
__device__ float g_cv[2 * DO];

// ---------------- helpers ----------------
__device__ __forceinline__ uint32_t smem_u32(const void* p) {
    uint32_t a;
    asm("{ .reg .u64 t; cvta.to.shared.u64 t, %1; cvt.u32.u64 %0, t; }" : "=r"(a) : "l"(p));
    return a;
}
__device__ __forceinline__ void ldsm4(uint32_t* r, uint32_t addr) {
    asm volatile("ldmatrix.sync.aligned.m8n8.x4.shared.b16 {%0,%1,%2,%3}, [%4];"
                 : "=r"(r[0]), "=r"(r[1]), "=r"(r[2]), "=r"(r[3]) : "r"(addr));
}
__device__ __forceinline__ void mma_f16(float* d, const uint32_t* a, const uint32_t* b) {
    asm volatile("mma.sync.aligned.m16n8k16.row.col.f32.f16.f16.f32 "
                 "{%0,%1,%2,%3}, {%4,%5,%6,%7}, {%8,%9}, {%0,%1,%2,%3};"
                 : "+f"(d[0]), "+f"(d[1]), "+f"(d[2]), "+f"(d[3])
                 : "r"(a[0]), "r"(a[1]), "r"(a[2]), "r"(a[3]), "r"(b[0]), "r"(b[1]));
}
__device__ __forceinline__ void cp16(uint32_t dst, const void* src) {
    asm volatile("cp.async.cg.shared.global [%0], [%1], 16;"
                 :: "r"(dst), "l"(__cvta_generic_to_global(src)));
}
#define CP_COMMIT() asm volatile("cp.async.commit_group;" ::: "memory")
#define CP_WAIT1()  asm volatile("cp.async.wait_group 1;" ::: "memory")

// ---------------- prep kernels ----------------
// 16 blocks (32 j each), 32x8 threads; coalesced weight reads
__global__ void prep_vec(const float* __restrict__ x,
                         const float* __restrict__ ea_wr, const float* __restrict__ ea_br,
                         const float* __restrict__ ea_wi, const float* __restrict__ ea_bi,
                         const float* __restrict__ eg_wr, const float* __restrict__ eg_br,
                         const float* __restrict__ eg_wi, const float* __restrict__ eg_bi) {
    __shared__ float xs[512];
    int tx = threadIdx.x, ty = threadIdx.y;
    int tid = ty * 32 + tx;
    int j = blockIdx.x * 32 + tx;
    for (int k = tid; k < 512; k += 256) xs[k] = x[k];
    __syncthreads();
    float sr = 0.f, si = 0.f;
    for (int k = ty; k < 512; k += 8) {
        float xv = xs[k];
        int r = k * 512 + j;
        sr += xv * (ea_wr[r] - eg_wr[r]);
        si += xv * (ea_wi[r] - eg_wi[r]);
    }
    __shared__ float shr[8][33], shi[8][33];
    shr[ty][tx] = sr; shi[ty][tx] = si;
    __syncthreads();
    if (ty == 0) {
#pragma unroll
        for (int q = 1; q < 8; q++) { sr += shr[q][tx]; si += shi[q][tx]; }
        g_vre[j] = sr + ea_br[j] - ea_bi[j] - eg_br[j] + eg_bi[j];
        g_vim[j] = si + ea_br[j] + ea_bi[j] - eg_br[j] - eg_bi[j];
    }
}

__global__ void prep_eA(const float* __restrict__ h_re, const float* __restrict__ h_im) {
    int idx = blockIdx.x * 256 + threadIdx.x;   // NC * 512 float4 slots
    if (idx < NC) g_t[idx] = 0.f;               // zero tension accumulator
    int n = idx >> 9;
    int k = (idx & 511) * 4;
    float4 v = (k < 1024)
        ? *reinterpret_cast<const float4*>(h_re + n * 1024 + k)
        : *reinterpret_cast<const float4*>(h_im + n * 1024 + (k - 1024));
    __half2 h0; h0.x = __float2half_rn(v.x); h0.y = __float2half_rn(v.y);
    __half2 h1; h1.x = __float2half_rn(v.z); h1.y = __float2half_rn(v.w);
    uint2 h;
    h.x = *reinterpret_cast<const uint32_t*>(&h0);
    h.y = *reinterpret_cast<const uint32_t*>(&h1);
    *reinterpret_cast<uint2*>(g_eA + (size_t)n * KENG + k) = h;
}

__global__ void transpose_e(const float* __restrict__ ea_wr, const float* __restrict__ ea_wi,
                            const float* __restrict__ eg_wr, const float* __restrict__ eg_wi) {
    __shared__ float tr[32][33], ti[32][33];
    int kb = blockIdx.x * 32, nb = blockIdx.y * 32;
    int tx = threadIdx.x, ty = threadIdx.y;
    for (int i = ty; i < 32; i += 8) {
        int k = kb + i, n = nb + tx;
        float re, im;
        if (k < 1024) {
            int r = (512 + k) * 512 + n;
            re = ea_wr[r] - eg_wr[r];
            im = ea_wi[r] - eg_wi[r];
        } else {
            int r = (k - 512) * 512 + n;
            re = -(ea_wi[r] - eg_wi[r]);
            im = ea_wr[r] - eg_wr[r];
        }
        tr[i][tx] = re; ti[i][tx] = im;
    }
    __syncthreads();
    for (int i = ty; i < 32; i += 8) {
        size_t o = (size_t)(nb + i) * KENG + kb + tx;
        g_eB[0][o] = __float2half_rn(tr[tx][i]);
        g_eB[1][o] = __float2half_rn(ti[tx][i]);
    }
}

__global__ void transpose_w(const float* __restrict__ w0, const float* __restrict__ w1,
                            const float* __restrict__ w2, const float* __restrict__ w3) {
    __shared__ float tile[32][33];
    int z = blockIdx.z;
    const float* src = (z == 0) ? w0 : (z == 1) ? w1 : (z == 2) ? w2 : w3;
    int kb = blockIdx.x * 32, nb = blockIdx.y * 32;
    int tx = threadIdx.x, ty = threadIdx.y;
    for (int i = ty; i < 32; i += 8) {
        int k = kb + i;
        tile[i][tx] = (k < GIN) ? src[(size_t)k * 1024 + nb + tx] : 0.f;
    }
    __syncthreads();
    for (int i = ty; i < 32; i += 8) {
        size_t o = (size_t)(nb + i) * LDT + kb + tx;
        g_WT[z][o] = __float2half_rn(tile[tx][i]);
    }
}

// ---------------- mma.sync fp16 GEMM (single-term, cp.async 2-stage) ----------------
// CTA tile 128x128, K-chunks of 64, 16 warps (4x4), 512 threads, 1 CTA/SM.
// stage layout (32KB): A@0 (16KB), B@16384 (16KB).
// EPI 0 also accumulates row sums of squares into g_t (tension, engine only).
#define STAGE_BYTES 32768
#define SMEM_GEMM_BYTES (2 * STAGE_BYTES)
template<int EPI>
__global__ void __launch_bounds__(512, 1) gemm_mma(
    const __half* __restrict__ A0, const __half* __restrict__ A1,
    const __half* __restrict__ B0, const __half* __restrict__ B1,
    int lda, int ldb, int K,
    float* __restrict__ C0, float* __restrict__ C1, int ldc,
    const float* __restrict__ vec0, const float* __restrict__ vec1,
    const float* __restrict__ Zp,
    const float* __restrict__ Hp0, const float* __restrict__ Hp1)
{
    extern __shared__ char smem[];
    uint32_t sb = smem_u32(smem);
    const int z = blockIdx.z;
    const __half* A = z ? A1 : A0;
    const __half* B = z ? B1 : B0;
    float* C = z ? C1 : C0;
    const float* vec = z ? vec1 : vec0;
    const float* Hp = z ? Hp1 : Hp0;

    const int tid = threadIdx.x;
    const int wid = tid >> 5, l = tid & 31;
    const int wm = wid & 3, wn = wid >> 2;   // 4 x 4 warps, 32x32 each
    const int bm = blockIdx.y * 128;
    const int bn = blockIdx.x * 128;

    float acc[2][4][4];
#pragma unroll
    for (int a = 0; a < 2; a++)
#pragma unroll
        for (int b = 0; b < 4; b++)
#pragma unroll
            for (int c = 0; c < 4; c++) acc[a][b][c] = 0.f;

    const int NK = K >> 6;

    auto load_stage = [&](int ch, int stage) {
        const int kc = ch << 6;
        const uint32_t base = sb + (uint32_t)stage * STAGE_BYTES;
#pragma unroll
        for (int j = 0; j < 2; j++) {
            const int within = j * 512 + tid;
            const int row = within >> 3, s = within & 7;
            const uint32_t swz = (uint32_t)((row * 128 + s * 16) ^ ((row & 7) << 4));
            cp16(base + swz,         A + (size_t)(bm + row) * lda + kc + s * 8);
            cp16(base + 16384 + swz, B + (size_t)(bn + row) * ldb + kc + s * 8);
        }
    };

    auto compute = [&](int stage) {
        const uint32_t base = sb + (uint32_t)stage * STAGE_BYTES;
#pragma unroll
        for (int ks = 0; ks < 4; ks++) {
            uint32_t ah[2][4], bhq[2][4];
            const int arow0 = wm * 32 + (l & 15);
            const int akb = ks * 32 + ((l >> 4) << 4);
#pragma unroll
            for (int mi = 0; mi < 2; mi++) {
                int row = arow0 + mi * 16;
                uint32_t ad = base + row * 128 + (akb ^ ((row & 7) << 4));
                ldsm4(ah[mi], ad);
            }
            const int brow0 = wn * 32 + (l & 7) + ((l >> 4) << 3);
            const int bkb = ks * 32 + (((l >> 3) & 1) << 4);
#pragma unroll
            for (int nj = 0; nj < 2; nj++) {
                int row = brow0 + nj * 16;
                uint32_t bd = base + 16384 + row * 128 + (bkb ^ ((row & 7) << 4));
                ldsm4(bhq[nj], bd);
            }
#pragma unroll
            for (int mi = 0; mi < 2; mi++)
#pragma unroll
                for (int ni = 0; ni < 4; ni++) {
                    const uint32_t* b2 = &bhq[ni >> 1][(ni & 1) * 2];
                    mma_f16(acc[mi][ni], ah[mi], b2);
                }
        }
    };

    load_stage(0, 0);
    CP_COMMIT();
    if (NK > 1) load_stage(1, 1);
    CP_COMMIT();

    for (int ch = 0; ch < NK; ch++) {
        CP_WAIT1();
        __syncthreads();
        compute(ch & 1);
        __syncthreads();
        if (ch + 2 < NK) load_stage(ch + 2, ch & 1);
        CP_COMMIT();
    }

    const int mr = bm + wm * 32 + (l >> 2);
    const int nc0 = bn + wn * 32 + ((l & 3) << 1);
    float rs[2][2] = {{0.f, 0.f}, {0.f, 0.f}};   // tension partials (EPI 0)
#pragma unroll
    for (int mi = 0; mi < 2; mi++) {
#pragma unroll
        for (int ni = 0; ni < 4; ni++) {
            int n = nc0 + ni * 8;
            float v0 = vec[n], v1 = vec[n + 1];
#pragma unroll
            for (int hh = 0; hh < 2; hh++) {
                int m = mr + mi * 16 + hh * 8;
                float e0 = acc[mi][ni][hh * 2 + 0] + v0;
                float e1 = acc[mi][ni][hh * 2 + 1] + v1;
                if (EPI == 0) rs[mi][hh] += e0 * e0 + e1 * e1;
                if (EPI == 1) {
                    e0 = 1.f / (1.f + expf(-e0));
                    e1 = 1.f / (1.f + expf(-e1));
                }
                if (EPI == 2) {
                    float c0 = tanhf(e0), c1 = tanhf(e1);
                    float z0 = Zp[(size_t)m * ldc + n], z1 = Zp[(size_t)m * ldc + n + 1];
                    float h0 = Hp[(size_t)m * ldc + n], h1 = Hp[(size_t)m * ldc + n + 1];
                    e0 = (1.f - z0) * h0 + z0 * c0;
                    e1 = (1.f - z1) * h1 + z1 * c1;
                }
                float2 o; o.x = e0; o.y = e1;
                *reinterpret_cast<float2*>(C + (size_t)m * ldc + n) = o;
            }
        }
    }
    if (EPI == 0) {
#pragma unroll
        for (int mi = 0; mi < 2; mi++)
#pragma unroll
            for (int hh = 0; hh < 2; hh++) {
                float s = rs[mi][hh];
                s += __shfl_xor_sync(0xffffffffu, s, 1);
                s += __shfl_xor_sync(0xffffffffu, s, 2);
                if ((l & 3) == 0)
                    atomicAdd(&g_t[mr + mi * 16 + hh * 8], s);
            }
    }
}

// ---------------- elementwise / reductions ----------------
__global__ void stats_k(float* __restrict__ out) {
    const float inv512 = 1.f / 512.f;
    int tid = threadIdx.x;
    float t0 = g_t[tid] * inv512, t1 = g_t[tid + 1024] * inv512;
    __shared__ float sh[1024];
    sh[tid] = fmaxf(t0, t1); __syncthreads();
    for (int s = 512; s > 0; s >>= 1) {
        if (tid < s) sh[tid] = fmaxf(sh[tid], sh[tid + s]);
        __syncthreads();
    }
    float mx = sh[0]; __syncthreads();
    sh[tid] = expf(t0 - mx) + expf(t1 - mx); __syncthreads();
    for (int s = 512; s > 0; s >>= 1) {
        if (tid < s) sh[tid] += sh[tid + s];
        __syncthreads();
    }
    float denom = sh[0]; __syncthreads();
    sh[tid] = t0 + t1; __syncthreads();
    for (int s = 512; s > 0; s >>= 1) {
        if (tid < s) sh[tid] += sh[tid + s];
        __syncthreads();
    }
    if (tid == 0) {
        g_stats[0] = mx;
        g_stats[1] = denom;
        out[512] = sh[0] * (1.f / 2048.f);
    }
    g_cv[tid] = 0.f;
}

// cm for all cols; also writes the mem-columns (j<=512) of the candidate inputs
__global__ void build_cm(const float* __restrict__ h_re, const float* __restrict__ h_im) {
    int idx = blockIdx.x * 256 + threadIdx.x;   // NC * LDT
    int n = idx / LDT;
    int j = idx - n * LDT;
    float v;
    if (j < 512) {
        float a = g_ore[n * 512 + j], b = g_oim[n * 512 + j];
        v = sqrtf(a * a + b * b);
        g_cr[idx] = __float2half_rn(a);
        g_ci[idx] = __float2half_rn(b);
    } else if (j == 512) {
        v = g_t[n] * (1.f / 512.f);
        g_cr[idx] = __float2half_rn(v);
        g_ci[idx] = __float2half_rn(0.f);
    } else if (j < GIN) {
        int jj = j - 513;
        float a = h_re[n * 1024 + jj], b = h_im[n * 1024 + jj];
        v = sqrtf(a * a + b * b);
    } else v = 0.f;
    g_cm[idx] = __float2half_rn(v);
}

// candidate inputs, cols [513, LDT): r*h (and zero padding)
__global__ void build_comb(const float* __restrict__ h_re, const float* __restrict__ h_im) {
    int n = blockIdx.x;            // 2048 rows
    int tid = threadIdx.x;         // 256
    for (int j = 513 + tid; j < LDT; j += 256) {
        float cr, ci;
        if (j < GIN) {
            int jj = j - 513;
            float rv = g_rr[n * 1024 + jj];
            cr = rv * h_re[n * 1024 + jj];
            ci = rv * h_im[n * 1024 + jj];
        } else { cr = 0.f; ci = 0.f; }
        int idx = n * LDT + j;
        g_cr[idx] = __float2half_rn(cr);
        g_ci[idx] = __float2half_rn(ci);
    }
}

// fmean phase 1: 128 blocks (comp*64 + f*8 + part), each sums 32 rows
__global__ void fmean1_k() {
    int b = blockIdx.x;
    int comp = b >> 6, f = (b >> 3) & 7, part = b & 7;
    int d = threadIdx.x;
    const float* src = comp ? g_nim : g_nre;
    int r0 = f * 256 + part * 32;
    float s = 0.f;
    for (int i = 0; i < 32; i++) s += src[(r0 + i) * 1024 + d];
    g_fmp[b * 1024 + d] = s;
}

// fmean phase 2 + gmean: 2 blocks (comp), 1024 threads
__global__ void fmean2_k() {
    int comp = blockIdx.x, d = threadIdx.x;
    float gsum = 0.f;
    for (int f = 0; f < 8; f++) {
        float s = 0.f;
        for (int part = 0; part < 8; part++)
            s += g_fmp[((comp * 8 + f) * 8 + part) * 1024 + d];
        s *= (1.f / 256.f);
        g_fm[(comp * 8 + f) * 1024 + d] = s;
        gsum += s;
    }
    g_gm[comp * 1024 + d] = gsum * 0.125f;
}

__global__ void apply_sync(float* __restrict__ out, const int* __restrict__ step) {
    int idx = blockIdx.x * 256 + threadIdx.x;
    int comp = idx >> 21;
    int rem = idx & ((1 << 21) - 1);
    int n = rem >> 10, d = rem & 1023;
    const float* src = comp ? g_nim : g_nre;
    float v = src[rem];
    int f = n >> 8;
    v = 0.85f * v + 0.15f * g_fm[(comp * 8 + f) * 1024 + d];
    if (step[0] > 5 && (n & 255) < 64)
        v = 0.85f * v + 0.15f * g_gm[comp * 1024 + d];
    out[513 + idx] = v;
}

__global__ void wsum_k() {
    int blk = blockIdx.x, tid = threadIdx.x;
    const float inv512 = 1.f / 512.f;
    float mx = g_stats[0];
    float inv = 1.f / g_stats[1];
    float a0 = 0.f, a1 = 0.f, a2 = 0.f, a3 = 0.f;
    for (int i = 0; i < 32; i++) {
        int n = blk * 32 + i;
        float w = expf(g_t[n] * inv512 - mx) * inv;
        a0 += w * g_ore[n * 512 + tid];
        a1 += w * g_ore[n * 512 + 256 + tid];
        a2 += w * g_oim[n * 512 + tid];
        a3 += w * g_oim[n * 512 + 256 + tid];
    }
    atomicAdd(&g_cv[tid], a0);
    atomicAdd(&g_cv[256 + tid], a1);
    atomicAdd(&g_cv[512 + tid], a2);
    atomicAdd(&g_cv[768 + tid], a3);
}

// one block per output column j; 256 threads split k
__global__ void pred_k(const float* __restrict__ oh_w, const float* __restrict__ oh_b,
                       float* __restrict__ out) {
    int j = blockIdx.x;
    int tid = threadIdx.x;
    float acc = 0.f;
#pragma unroll
    for (int q = 0; q < 4; q++) {
        int k = q * 256 + tid;
        acc += g_cv[k] * oh_w[(size_t)k * 512 + j];
    }
    __shared__ float sh[256];
    sh[tid] = acc; __syncthreads();
    for (int s = 128; s > 0; s >>= 1) {
        if (tid < s) sh[tid] += sh[tid + s];
        __syncthreads();
    }
    if (tid == 0) out[j] = sh[0] + oh_b[j];
}

// ---------------- launch ----------------
extern "C" void kernel_launch(void* const* d_in, const int* in_sizes, int n_in,
                              void* d_out, int out_size) {
    (void)in_sizes; (void)n_in; (void)out_size;
    const float* x     = (const float*)d_in[0];
    const float* h_re  = (const float*)d_in[1];
    const float* h_im  = (const float*)d_in[2];
    const float* ea_wr = (const float*)d_in[3];
    const float* ea_br = (const float*)d_in[4];
    const float* ea_wi = (const float*)d_in[5];
    const float* ea_bi = (const float*)d_in[6];
    const float* eg_wr = (const float*)d_in[7];
    const float* eg_br = (const float*)d_in[8];
    const float* eg_wi = (const float*)d_in[9];
    const float* eg_bi = (const float*)d_in[10];
    const float* gz_w  = (const float*)d_in[11];
    const float* gz_b  = (const float*)d_in[12];
    const float* gr_w  = (const float*)d_in[13];
    const float* gr_b  = (const float*)d_in[14];
    const float* ghr_w = (const float*)d_in[15];
    const float* ghr_b = (const float*)d_in[16];
    const float* ghi_w = (const float*)d_in[17];
    const float* ghi_b = (const float*)d_in[18];
    const float* oh_w  = (const float*)d_in[19];
    const float* oh_b  = (const float*)d_in[20];
    const int*   step  = (const int*)d_in[21];
    float* out = (float*)d_out;

    __half *pEA, *pEB, *pWT, *pCm, *pCr, *pCi;
    float *pVre, *pVim, *pOre, *pOim, *pZ, *pRr, *pNre, *pNim;
    cudaGetSymbolAddress((void**)&pEA,  g_eA);
    cudaGetSymbolAddress((void**)&pEB,  g_eB);
    cudaGetSymbolAddress((void**)&pWT,  g_WT);
    cudaGetSymbolAddress((void**)&pCm,  g_cm);
    cudaGetSymbolAddress((void**)&pCr,  g_cr);
    cudaGetSymbolAddress((void**)&pCi,  g_ci);
    cudaGetSymbolAddress((void**)&pVre, g_vre);
    cudaGetSymbolAddress((void**)&pVim, g_vim);
    cudaGetSymbolAddress((void**)&pOre, g_ore);
    cudaGetSymbolAddress((void**)&pOim, g_oim);
    cudaGetSymbolAddress((void**)&pZ,   g_z);
    cudaGetSymbolAddress((void**)&pRr,  g_rr);
    cudaGetSymbolAddress((void**)&pNre, g_nre);
    cudaGetSymbolAddress((void**)&pNim, g_nim);

    cudaFuncSetAttribute((const void*)gemm_mma<0>, cudaFuncAttributeMaxDynamicSharedMemorySize, SMEM_GEMM_BYTES);
    cudaFuncSetAttribute((const void*)gemm_mma<1>, cudaFuncAttributeMaxDynamicSharedMemorySize, SMEM_GEMM_BYTES);
    cudaFuncSetAttribute((const void*)gemm_mma<2>, cudaFuncAttributeMaxDynamicSharedMemorySize, SMEM_GEMM_BYTES);

    const size_t EB = (size_t)DO * KENG;
    const size_t WB = (size_t)DH * LDT;

    transpose_e<<<dim3(64, 16), dim3(32, 8)>>>(ea_wr, ea_wi, eg_wr, eg_wi);
    transpose_w<<<dim3(LDT / 32, 32, 4), dim3(32, 8)>>>(gz_w, gr_w, ghr_w, ghi_w);
    prep_eA<<<4096, 256>>>(h_re, h_im);
    prep_vec<<<16, dim3(32, 8)>>>(x, ea_wr, ea_br, ea_wi, ea_bi, eg_wr, eg_br, eg_wi, eg_bi);

    // engine re/im fused (1-term A); epilogue accumulates tension into g_t
    gemm_mma<0><<<dim3(4, 16, 2), 512, SMEM_GEMM_BYTES>>>(
        pEA, pEA,
        pEB, pEB + EB,
        KENG, KENG, KENG,
        pOre, pOim, 512,
        pVre, pVim, nullptr, nullptr, nullptr);

    build_cm<<<(NC * LDT) / 256, 256>>>(h_re, h_im);
    stats_k<<<1, 1024>>>(out);

    // GRU z & r fused (1-term A)
    gemm_mma<1><<<dim3(8, 16, 2), 512, SMEM_GEMM_BYTES>>>(
        pCm, pCm,
        pWT + 0 * WB, pWT + 1 * WB,
        LDT, LDT, LDT,
        pZ, pRr, 1024,
        gz_b, gr_b, nullptr, nullptr, nullptr);

    build_comb<<<NC, 256>>>(h_re, h_im);
    // GRU candidates fused (1-term A)
    gemm_mma<2><<<dim3(8, 16, 2), 512, SMEM_GEMM_BYTES>>>(
        pCr, pCi,
        pWT + 2 * WB, pWT + 3 * WB,
        LDT, LDT, LDT,
        pNre, pNim, 1024,
        ghr_b, ghi_b, pZ, h_re, h_im);

    fmean1_k<<<128, 1024>>>();
    fmean2_k<<<2, 1024>>>();
    apply_sync<<<16384, 256>>>(out, step);

    wsum_k<<<64, 256>>>();
    pred_k<<<512, 256>>>(oh_w, oh_b, out);
}

// round 12
// speedup vs baseline: 1.0892x; 1.0892x over previous
#include <cuda_runtime.h>
#include <cuda_fp16.h>
#include <cstdint>
#include <math.h>

#define NC 2048
#define DH 1024
#define DO 512
#define GIN 1537
#define LDT 1600           // GRU K padded to multiple of 64
#define KENG 2048

// ---------------- scratch ----------------
__device__ __half g_eA[NC * KENG];                        // engine A (single fp16)
__device__ __half g_eB[2][DO * KENG];                     // engine B^T re/im (single fp16)
__device__ __half g_WT[4][DH * LDT];                      // GRU weights^T (single fp16)
__device__ __half g_cm[NC * LDT];                         // GRU gate input
__device__ __half g_cr[NC * LDT];                         // candidate re input
__device__ __half g_ci[NC * LDT];                         // candidate im input
__device__ float g_vre[DO];
__device__ float g_vim[DO];
__device__ float g_ore[NC * DO];
__device__ float g_oim[NC * DO];
__device__ float g_t[NC];                 // raw sum of squares (atomicAdd target)
__device__ float g_stats[2];
__device__ float g_z[NC * DH];
__device__ float g_rr[NC * DH];
__device__ float g_nre[NC * DH];
__device__ float g_nim[NC * DH];
__device__ float g_fmp[128 * DH];         // fmean partials
__device__ float g_fm[2 * 8 * DH];
__device__ float g_gm[2 * DH];
__device__ float g_cv[2 * DO];

// ---------------- helpers ----------------
__device__ __forceinline__ uint32_t smem_u32(const void* p) {
    uint32_t a;
    asm("{ .reg .u64 t; cvta.to.shared.u64 t, %1; cvt.u32.u64 %0, t; }" : "=r"(a) : "l"(p));
    return a;
}
__device__ __forceinline__ void ldsm4(uint32_t* r, uint32_t addr) {
    asm volatile("ldmatrix.sync.aligned.m8n8.x4.shared.b16 {%0,%1,%2,%3}, [%4];"
                 : "=r"(r[0]), "=r"(r[1]), "=r"(r[2]), "=r"(r[3]) : "r"(addr));
}
__device__ __forceinline__ void mma_f16(float* d, const uint32_t* a, const uint32_t* b) {
    asm volatile("mma.sync.aligned.m16n8k16.row.col.f32.f16.f16.f32 "
                 "{%0,%1,%2,%3}, {%4,%5,%6,%7}, {%8,%9}, {%0,%1,%2,%3};"
                 : "+f"(d[0]), "+f"(d[1]), "+f"(d[2]), "+f"(d[3])
                 : "r"(a[0]), "r"(a[1]), "r"(a[2]), "r"(a[3]), "r"(b[0]), "r"(b[1]));
}
__device__ __forceinline__ void cp16(uint32_t dst, const void* src) {
    asm volatile("cp.async.cg.shared.global [%0], [%1], 16;"
                 :: "r"(dst), "l"(__cvta_generic_to_global(src)));
}
#define CP_COMMIT() asm volatile("cp.async.commit_group;" ::: "memory")
#define CP_WAIT1()  asm volatile("cp.async.wait_group 1;" ::: "memory")

// ---------------- prep kernels ----------------
// grid (16 j-groups, 16 k-chunks), block 32x8; coalesced reads + atomic partials
__global__ void prep_vec(const float* __restrict__ x,
                         const float* __restrict__ ea_wr, const float* __restrict__ ea_br,
                         const float* __restrict__ ea_wi, const float* __restrict__ ea_bi,
                         const float* __restrict__ eg_wr, const float* __restrict__ eg_br,
                         const float* __restrict__ eg_wi, const float* __restrict__ eg_bi) {
    int tx = threadIdx.x, ty = threadIdx.y;
    int j = blockIdx.x * 32 + tx;
    int k0 = blockIdx.y * 32;
    float sr = 0.f, si = 0.f;
#pragma unroll
    for (int kk = 0; kk < 4; kk++) {
        int k = k0 + ty + kk * 8;
        float xv = x[k];
        int r = k * 512 + j;
        sr += xv * (ea_wr[r] - eg_wr[r]);
        si += xv * (ea_wi[r] - eg_wi[r]);
    }
    __shared__ float shr[8][33], shi[8][33];
    shr[ty][tx] = sr; shi[ty][tx] = si;
    __syncthreads();
    if (ty == 0) {
#pragma unroll
        for (int q = 1; q < 8; q++) { sr += shr[q][tx]; si += shi[q][tx]; }
        if (blockIdx.y == 0) {
            sr += ea_br[j] - ea_bi[j] - eg_br[j] + eg_bi[j];
            si += ea_br[j] + ea_bi[j] - eg_br[j] - eg_bi[j];
        }
        atomicAdd(&g_vre[j], sr);
        atomicAdd(&g_vim[j], si);
    }
}

__global__ void prep_eA(const float* __restrict__ h_re, const float* __restrict__ h_im) {
    int idx = blockIdx.x * 256 + threadIdx.x;   // NC * 512 float4 slots
    if (idx < NC) g_t[idx] = 0.f;               // zero tension accumulator
    if (idx < DO) { g_vre[idx] = 0.f; g_vim[idx] = 0.f; }
    int n = idx >> 9;
    int k = (idx & 511) * 4;
    float4 v = (k < 1024)
        ? *reinterpret_cast<const float4*>(h_re + n * 1024 + k)
        : *reinterpret_cast<const float4*>(h_im + n * 1024 + (k - 1024));
    __half2 h0; h0.x = __float2half_rn(v.x); h0.y = __float2half_rn(v.y);
    __half2 h1; h1.x = __float2half_rn(v.z); h1.y = __float2half_rn(v.w);
    uint2 h;
    h.x = *reinterpret_cast<const uint32_t*>(&h0);
    h.y = *reinterpret_cast<const uint32_t*>(&h1);
    *reinterpret_cast<uint2*>(g_eA + (size_t)n * KENG + k) = h;
}

__global__ void transpose_e(const float* __restrict__ ea_wr, const float* __restrict__ ea_wi,
                            const float* __restrict__ eg_wr, const float* __restrict__ eg_wi) {
    __shared__ float tr[32][33], ti[32][33];
    int kb = blockIdx.x * 32, nb = blockIdx.y * 32;
    int tx = threadIdx.x, ty = threadIdx.y;
    for (int i = ty; i < 32; i += 8) {
        int k = kb + i, n = nb + tx;
        float re, im;
        if (k < 1024) {
            int r = (512 + k) * 512 + n;
            re = ea_wr[r] - eg_wr[r];
            im = ea_wi[r] - eg_wi[r];
        } else {
            int r = (k - 512) * 512 + n;
            re = -(ea_wi[r] - eg_wi[r]);
            im = ea_wr[r] - eg_wr[r];
        }
        tr[i][tx] = re; ti[i][tx] = im;
    }
    __syncthreads();
    for (int i = ty; i < 32; i += 8) {
        size_t o = (size_t)(nb + i) * KENG + kb + tx;
        g_eB[0][o] = __float2half_rn(tr[tx][i]);
        g_eB[1][o] = __float2half_rn(ti[tx][i]);
    }
}

__global__ void transpose_w(const float* __restrict__ w0, const float* __restrict__ w1,
                            const float* __restrict__ w2, const float* __restrict__ w3) {
    __shared__ float tile[32][33];
    int z = blockIdx.z;
    const float* src = (z == 0) ? w0 : (z == 1) ? w1 : (z == 2) ? w2 : w3;
    int kb = blockIdx.x * 32, nb = blockIdx.y * 32;
    int tx = threadIdx.x, ty = threadIdx.y;
    for (int i = ty; i < 32; i += 8) {
        int k = kb + i;
        tile[i][tx] = (k < GIN) ? src[(size_t)k * 1024 + nb + tx] : 0.f;
    }
    __syncthreads();
    for (int i = ty; i < 32; i += 8) {
        size_t o = (size_t)(nb + i) * LDT + kb + tx;
        g_WT[z][o] = __float2half_rn(tile[tx][i]);
    }
}

// ---------------- mma.sync fp16 GEMM (single-term, cp.async 2-stage) ----------------
// CTA tile 128x128, K-chunks of 64, 16 warps (4x4), 512 threads, 1 CTA/SM.
// stage layout (32KB): A@0 (16KB), B@16384 (16KB).
// EPI 0 also accumulates row sums of squares into g_t (tension, engine only).
#define STAGE_BYTES 32768
#define SMEM_GEMM_BYTES (2 * STAGE_BYTES)
template<int EPI>
__global__ void __launch_bounds__(512, 1) gemm_mma(
    const __half* __restrict__ A0, const __half* __restrict__ A1,
    const __half* __restrict__ B0, const __half* __restrict__ B1,
    int lda, int ldb, int K,
    float* __restrict__ C0, float* __restrict__ C1, int ldc,
    const float* __restrict__ vec0, const float* __restrict__ vec1,
    const float* __restrict__ Zp,
    const float* __restrict__ Hp0, const float* __restrict__ Hp1)
{
    extern __shared__ char smem[];
    uint32_t sb = smem_u32(smem);
    const int z = blockIdx.z;
    const __half* A = z ? A1 : A0;
    const __half* B = z ? B1 : B0;
    float* C = z ? C1 : C0;
    const float* vec = z ? vec1 : vec0;
    const float* Hp = z ? Hp1 : Hp0;

    const int tid = threadIdx.x;
    const int wid = tid >> 5, l = tid & 31;
    const int wm = wid & 3, wn = wid >> 2;   // 4 x 4 warps, 32x32 each
    const int bm = blockIdx.y * 128;
    const int bn = blockIdx.x * 128;

    float acc[2][4][4];
#pragma unroll
    for (int a = 0; a < 2; a++)
#pragma unroll
        for (int b = 0; b < 4; b++)
#pragma unroll
            for (int c = 0; c < 4; c++) acc[a][b][c] = 0.f;

    const int NK = K >> 6;

    auto load_stage = [&](int ch, int stage) {
        const int kc = ch << 6;
        const uint32_t base = sb + (uint32_t)stage * STAGE_BYTES;
#pragma unroll
        for (int j = 0; j < 2; j++) {
            const int within = j * 512 + tid;
            const int row = within >> 3, s = within & 7;
            const uint32_t swz = (uint32_t)((row * 128 + s * 16) ^ ((row & 7) << 4));
            cp16(base + swz,         A + (size_t)(bm + row) * lda + kc + s * 8);
            cp16(base + 16384 + swz, B + (size_t)(bn + row) * ldb + kc + s * 8);
        }
    };

    auto compute = [&](int stage) {
        const uint32_t base = sb + (uint32_t)stage * STAGE_BYTES;
#pragma unroll
        for (int ks = 0; ks < 4; ks++) {
            uint32_t ah[2][4], bhq[2][4];
            const int arow0 = wm * 32 + (l & 15);
            const int akb = ks * 32 + ((l >> 4) << 4);
#pragma unroll
            for (int mi = 0; mi < 2; mi++) {
                int row = arow0 + mi * 16;
                uint32_t ad = base + row * 128 + (akb ^ ((row & 7) << 4));
                ldsm4(ah[mi], ad);
            }
            const int brow0 = wn * 32 + (l & 7) + ((l >> 4) << 3);
            const int bkb = ks * 32 + (((l >> 3) & 1) << 4);
#pragma unroll
            for (int nj = 0; nj < 2; nj++) {
                int row = brow0 + nj * 16;
                uint32_t bd = base + 16384 + row * 128 + (bkb ^ ((row & 7) << 4));
                ldsm4(bhq[nj], bd);
            }
#pragma unroll
            for (int mi = 0; mi < 2; mi++)
#pragma unroll
                for (int ni = 0; ni < 4; ni++) {
                    const uint32_t* b2 = &bhq[ni >> 1][(ni & 1) * 2];
                    mma_f16(acc[mi][ni], ah[mi], b2);
                }
        }
    };

    load_stage(0, 0);
    CP_COMMIT();
    if (NK > 1) load_stage(1, 1);
    CP_COMMIT();

    for (int ch = 0; ch < NK; ch++) {
        CP_WAIT1();
        __syncthreads();
        compute(ch & 1);
        __syncthreads();
        if (ch + 2 < NK) load_stage(ch + 2, ch & 1);
        CP_COMMIT();
    }

    const int mr = bm + wm * 32 + (l >> 2);
    const int nc0 = bn + wn * 32 + ((l & 3) << 1);
    float rs[2][2] = {{0.f, 0.f}, {0.f, 0.f}};   // tension partials (EPI 0)
#pragma unroll
    for (int mi = 0; mi < 2; mi++) {
#pragma unroll
        for (int ni = 0; ni < 4; ni++) {
            int n = nc0 + ni * 8;
            float v0 = vec[n], v1 = vec[n + 1];
#pragma unroll
            for (int hh = 0; hh < 2; hh++) {
                int m = mr + mi * 16 + hh * 8;
                float e0 = acc[mi][ni][hh * 2 + 0] + v0;
                float e1 = acc[mi][ni][hh * 2 + 1] + v1;
                if (EPI == 0) rs[mi][hh] += e0 * e0 + e1 * e1;
                if (EPI == 1) {
                    e0 = 1.f / (1.f + expf(-e0));
                    e1 = 1.f / (1.f + expf(-e1));
                }
                if (EPI == 2) {
                    float c0 = tanhf(e0), c1 = tanhf(e1);
                    float z0 = Zp[(size_t)m * ldc + n], z1 = Zp[(size_t)m * ldc + n + 1];
                    float h0 = Hp[(size_t)m * ldc + n], h1 = Hp[(size_t)m * ldc + n + 1];
                    e0 = (1.f - z0) * h0 + z0 * c0;
                    e1 = (1.f - z1) * h1 + z1 * c1;
                }
                float2 o; o.x = e0; o.y = e1;
                *reinterpret_cast<float2*>(C + (size_t)m * ldc + n) = o;
            }
        }
    }
    if (EPI == 0) {
#pragma unroll
        for (int mi = 0; mi < 2; mi++)
#pragma unroll
            for (int hh = 0; hh < 2; hh++) {
                float s = rs[mi][hh];
                s += __shfl_xor_sync(0xffffffffu, s, 1);
                s += __shfl_xor_sync(0xffffffffu, s, 2);
                if ((l & 3) == 0)
                    atomicAdd(&g_t[mr + mi * 16 + hh * 8], s);
            }
    }
}

// ---------------- elementwise / reductions ----------------
__global__ void stats_k(float* __restrict__ out) {
    const float inv512 = 1.f / 512.f;
    int tid = threadIdx.x;
    float t0 = g_t[tid] * inv512, t1 = g_t[tid + 1024] * inv512;
    __shared__ float sh[1024];
    sh[tid] = fmaxf(t0, t1); __syncthreads();
    for (int s = 512; s > 0; s >>= 1) {
        if (tid < s) sh[tid] = fmaxf(sh[tid], sh[tid + s]);
        __syncthreads();
    }
    float mx = sh[0]; __syncthreads();
    sh[tid] = expf(t0 - mx) + expf(t1 - mx); __syncthreads();
    for (int s = 512; s > 0; s >>= 1) {
        if (tid < s) sh[tid] += sh[tid + s];
        __syncthreads();
    }
    float denom = sh[0]; __syncthreads();
    sh[tid] = t0 + t1; __syncthreads();
    for (int s = 512; s > 0; s >>= 1) {
        if (tid < s) sh[tid] += sh[tid + s];
        __syncthreads();
    }
    if (tid == 0) {
        g_stats[0] = mx;
        g_stats[1] = denom;
        out[512] = sh[0] * (1.f / 2048.f);
    }
    g_cv[tid] = 0.f;
}

// cm for all cols; also writes the mem-columns (j<=512) of the candidate inputs
__global__ void build_cm(const float* __restrict__ h_re, const float* __restrict__ h_im) {
    int idx = blockIdx.x * 256 + threadIdx.x;   // NC * LDT
    int n = idx / LDT;
    int j = idx - n * LDT;
    float v;
    if (j < 512) {
        float a = g_ore[n * 512 + j], b = g_oim[n * 512 + j];
        v = sqrtf(a * a + b * b);
        g_cr[idx] = __float2half_rn(a);
        g_ci[idx] = __float2half_rn(b);
    } else if (j == 512) {
        v = g_t[n] * (1.f / 512.f);
        g_cr[idx] = __float2half_rn(v);
        g_ci[idx] = __float2half_rn(0.f);
    } else if (j < GIN) {
        int jj = j - 513;
        float a = h_re[n * 1024 + jj], b = h_im[n * 1024 + jj];
        v = sqrtf(a * a + b * b);
    } else v = 0.f;
    g_cm[idx] = __float2half_rn(v);
}

// candidate inputs, cols [513, LDT): r*h (and zero padding)
__global__ void build_comb(const float* __restrict__ h_re, const float* __restrict__ h_im) {
    int n = blockIdx.x;            // 2048 rows
    int tid = threadIdx.x;         // 256
    for (int j = 513 + tid; j < LDT; j += 256) {
        float cr, ci;
        if (j < GIN) {
            int jj = j - 513;
            float rv = g_rr[n * 1024 + jj];
            cr = rv * h_re[n * 1024 + jj];
            ci = rv * h_im[n * 1024 + jj];
        } else { cr = 0.f; ci = 0.f; }
        int idx = n * LDT + j;
        g_cr[idx] = __float2half_rn(cr);
        g_ci[idx] = __float2half_rn(ci);
    }
}

// fmean phase 1: 128 blocks (comp*64 + f*8 + part), each sums 32 rows
__global__ void fmean1_k() {
    int b = blockIdx.x;
    int comp = b >> 6, f = (b >> 3) & 7, part = b & 7;
    int d = threadIdx.x;
    const float* src = comp ? g_nim : g_nre;
    int r0 = f * 256 + part * 32;
    float s = 0.f;
    for (int i = 0; i < 32; i++) s += src[(r0 + i) * 1024 + d];
    g_fmp[b * 1024 + d] = s;
}

// fmean phase 2 + gmean: 2 blocks (comp), 1024 threads
__global__ void fmean2_k() {
    int comp = blockIdx.x, d = threadIdx.x;
    float gsum = 0.f;
    for (int f = 0; f < 8; f++) {
        float s = 0.f;
        for (int part = 0; part < 8; part++)
            s += g_fmp[((comp * 8 + f) * 8 + part) * 1024 + d];
        s *= (1.f / 256.f);
        g_fm[(comp * 8 + f) * 1024 + d] = s;
        gsum += s;
    }
    g_gm[comp * 1024 + d] = gsum * 0.125f;
}

__global__ void apply_sync(float* __restrict__ out, const int* __restrict__ step) {
    int idx = blockIdx.x * 256 + threadIdx.x;
    int comp = idx >> 21;
    int rem = idx & ((1 << 21) - 1);
    int n = rem >> 10, d = rem & 1023;
    const float* src = comp ? g_nim : g_nre;
    float v = src[rem];
    int f = n >> 8;
    v = 0.85f * v + 0.15f * g_fm[(comp * 8 + f) * 1024 + d];
    if (step[0] > 5 && (n & 255) < 64)
        v = 0.85f * v + 0.15f * g_gm[comp * 1024 + d];
    out[513 + idx] = v;
}

__global__ void wsum_k() {
    int blk = blockIdx.x, tid = threadIdx.x;
    const float inv512 = 1.f / 512.f;
    float mx = g_stats[0];
    float inv = 1.f / g_stats[1];
    float a0 = 0.f, a1 = 0.f, a2 = 0.f, a3 = 0.f;
    for (int i = 0; i < 32; i++) {
        int n = blk * 32 + i;
        float w = expf(g_t[n] * inv512 - mx) * inv;
        a0 += w * g_ore[n * 512 + tid];
        a1 += w * g_ore[n * 512 + 256 + tid];
        a2 += w * g_oim[n * 512 + tid];
        a3 += w * g_oim[n * 512 + 256 + tid];
    }
    atomicAdd(&g_cv[tid], a0);
    atomicAdd(&g_cv[256 + tid], a1);
    atomicAdd(&g_cv[512 + tid], a2);
    atomicAdd(&g_cv[768 + tid], a3);
}

// one block per output column j; 256 threads split k
__global__ void pred_k(const float* __restrict__ oh_w, const float* __restrict__ oh_b,
                       float* __restrict__ out) {
    int j = blockIdx.x;
    int tid = threadIdx.x;
    float acc = 0.f;
#pragma unroll
    for (int q = 0; q < 4; q++) {
        int k = q * 256 + tid;
        acc += g_cv[k] * oh_w[(size_t)k * 512 + j];
    }
    __shared__ float sh[256];
    sh[tid] = acc; __syncthreads();
    for (int s = 128; s > 0; s >>= 1) {
        if (tid < s) sh[tid] += sh[tid + s];
        __syncthreads();
    }
    if (tid == 0) out[j] = sh[0] + oh_b[j];
}

// ---------------- launch ----------------
extern "C" void kernel_launch(void* const* d_in, const int* in_sizes, int n_in,
                              void* d_out, int out_size) {
    (void)in_sizes; (void)n_in; (void)out_size;
    const float* x     = (const float*)d_in[0];
    const float* h_re  = (const float*)d_in[1];
    const float* h_im  = (const float*)d_in[2];
    const float* ea_wr = (const float*)d_in[3];
    const float* ea_br = (const float*)d_in[4];
    const float* ea_wi = (const float*)d_in[5];
    const float* ea_bi = (const float*)d_in[6];
    const float* eg_wr = (const float*)d_in[7];
    const float* eg_br = (const float*)d_in[8];
    const float* eg_wi = (const float*)d_in[9];
    const float* eg_bi = (const float*)d_in[10];
    const float* gz_w  = (const float*)d_in[11];
    const float* gz_b  = (const float*)d_in[12];
    const float* gr_w  = (const float*)d_in[13];
    const float* gr_b  = (const float*)d_in[14];
    const float* ghr_w = (const float*)d_in[15];
    const float* ghr_b = (const float*)d_in[16];
    const float* ghi_w = (const float*)d_in[17];
    const float* ghi_b = (const float*)d_in[18];
    const float* oh_w  = (const float*)d_in[19];
    const float* oh_b  = (const float*)d_in[20];
    const int*   step  = (const int*)d_in[21];
    float* out = (float*)d_out;

    __half *pEA, *pEB, *pWT, *pCm, *pCr, *pCi;
    float *pVre, *pVim, *pOre, *pOim, *pZ, *pRr, *pNre, *pNim;
    cudaGetSymbolAddress((void**)&pEA,  g_eA);
    cudaGetSymbolAddress((void**)&pEB,  g_eB);
    cudaGetSymbolAddress((void**)&pWT,  g_WT);
    cudaGetSymbolAddress((void**)&pCm,  g_cm);
    cudaGetSymbolAddress((void**)&pCr,  g_cr);
    cudaGetSymbolAddress((void**)&pCi,  g_ci);
    cudaGetSymbolAddress((void**)&pVre, g_vre);
    cudaGetSymbolAddress((void**)&pVim, g_vim);
    cudaGetSymbolAddress((void**)&pOre, g_ore);
    cudaGetSymbolAddress((void**)&pOim, g_oim);
    cudaGetSymbolAddress((void**)&pZ,   g_z);
    cudaGetSymbolAddress((void**)&pRr,  g_rr);
    cudaGetSymbolAddress((void**)&pNre, g_nre);
    cudaGetSymbolAddress((void**)&pNim, g_nim);

    cudaFuncSetAttribute((const void*)gemm_mma<0>, cudaFuncAttributeMaxDynamicSharedMemorySize, SMEM_GEMM_BYTES);
    cudaFuncSetAttribute((const void*)gemm_mma<1>, cudaFuncAttributeMaxDynamicSharedMemorySize, SMEM_GEMM_BYTES);
    cudaFuncSetAttribute((const void*)gemm_mma<2>, cudaFuncAttributeMaxDynamicSharedMemorySize, SMEM_GEMM_BYTES);

    const size_t EB = (size_t)DO * KENG;
    const size_t WB = (size_t)DH * LDT;

    transpose_e<<<dim3(64, 16), dim3(32, 8)>>>(ea_wr, ea_wi, eg_wr, eg_wi);
    transpose_w<<<dim3(LDT / 32, 32, 4), dim3(32, 8)>>>(gz_w, gr_w, ghr_w, ghi_w);
    prep_eA<<<4096, 256>>>(h_re, h_im);   // also zeroes g_t, g_vre, g_vim
    prep_vec<<<dim3(16, 16), dim3(32, 8)>>>(x, ea_wr, ea_br, ea_wi, ea_bi, eg_wr, eg_br, eg_wi, eg_bi);

    // engine re/im fused (1-term A); epilogue accumulates tension into g_t
    gemm_mma<0><<<dim3(4, 16, 2), 512, SMEM_GEMM_BYTES>>>(
        pEA, pEA,
        pEB, pEB + EB,
        KENG, KENG, KENG,
        pOre, pOim, 512,
        pVre, pVim, nullptr, nullptr, nullptr);

    build_cm<<<(NC * LDT) / 256, 256>>>(h_re, h_im);
    stats_k<<<1, 1024>>>(out);

    // GRU z & r fused (1-term A)
    gemm_mma<1><<<dim3(8, 16, 2), 512, SMEM_GEMM_BYTES>>>(
        pCm, pCm,
        pWT + 0 * WB, pWT + 1 * WB,
        LDT, LDT, LDT,
        pZ, pRr, 1024,
        gz_b, gr_b, nullptr, nullptr, nullptr);

    build_comb<<<NC, 256>>>(h_re, h_im);
    // GRU candidates fused (1-term A)
    gemm_mma<2><<<dim3(8, 16, 2), 512, SMEM_GEMM_BYTES>>>(
        pCr, pCi,
        pWT + 2 * WB, pWT + 3 * WB,
        LDT, LDT, LDT,
        pNre, pNim, 1024,
        ghr_b, ghi_b, pZ, h_re, h_im);

    fmean1_k<<<128, 1024>>>();
    fmean2_k<<<2, 1024>>>();
    apply_sync<<<16384, 256>>>(out, step);

    wsum_k<<<64, 256>>>();
    pred_k<<<512, 256>>>(oh_w, oh_b, out);
}

// round 14
// speedup vs baseline: 1.2876x; 1.1822x over previous
#include <cuda_runtime.h>
#include <cuda_fp16.h>
#include <cstdint>
#include <math.h>

#define NC 2048
#define DH 1024
#define DO 512
#define GIN 1537
#define LDT 1600           // GRU K padded to multiple of 64
#define KENG 2048

// ---------------- scratch ----------------
__device__ __half g_eA[NC * KENG];                        // engine A (single fp16)
__device__ __half g_eB[2][DO * KENG];                     // engine B^T re/im (single fp16)
__device__ __half g_WT[4][DH * LDT];                      // GRU weights^T (single fp16)
__device__ __half g_cm[NC * LDT];                         // GRU gate input
__device__ __half g_cr[NC * LDT];                         // candidate re input
__device__ __half g_ci[NC * LDT];                         // candidate im input
__device__ float g_vre[DO];
__device__ float g_vim[DO];
__device__ float g_ore[NC * DO];
__device__ float g_oim[NC * DO];
__device__ float g_t[NC];                 // raw sum of squares (atomicAdd target)
__device__ float g_stats[2];
__device__ float g_z[NC * DH];
__device__ float g_rr[NC * DH];
__device__ float g_nre[NC * DH];
__device__ float g_nim[NC * DH];
__device__ float g_fmp[128 * DH];         // fmean partials
__device__ float g_fm[2 * 8 * DH];
__device__ float g_gm[2 * DH];
__device__ float g_cv[2 * DO];

// ---------------- helpers ----------------
__device__ __forceinline__ uint32_t smem_u32(const void* p) {
    uint32_t a;
    asm("{ .reg .u64 t; cvta.to.shared.u64 t, %1; cvt.u32.u64 %0, t; }" : "=r"(a) : "l"(p));
    return a;
}
__device__ __forceinline__ void ldsm4(uint32_t* r, uint32_t addr) {
    asm volatile("ldmatrix.sync.aligned.m8n8.x4.shared.b16 {%0,%1,%2,%3}, [%4];"
                 : "=r"(r[0]), "=r"(r[1]), "=r"(r[2]), "=r"(r[3]) : "r"(addr));
}
__device__ __forceinline__ void mma_f16(float* d, const uint32_t* a, const uint32_t* b) {
    asm volatile("mma.sync.aligned.m16n8k16.row.col.f32.f16.f16.f32 "
                 "{%0,%1,%2,%3}, {%4,%5,%6,%7}, {%8,%9}, {%0,%1,%2,%3};"
                 : "+f"(d[0]), "+f"(d[1]), "+f"(d[2]), "+f"(d[3])
                 : "r"(a[0]), "r"(a[1]), "r"(a[2]), "r"(a[3]), "r"(b[0]), "r"(b[1]));
}
__device__ __forceinline__ void cp16(uint32_t dst, const void* src) {
    asm volatile("cp.async.cg.shared.global [%0], [%1], 16;"
                 :: "r"(dst), "l"(__cvta_generic_to_global(src)));
}
#define CP_COMMIT() asm volatile("cp.async.commit_group;" ::: "memory")
#define CP_WAIT1()  asm volatile("cp.async.wait_group 1;" ::: "memory")

// ---------------- prep kernels ----------------
// grid (16 j-groups, 16 k-chunks), block 32x8; coalesced reads + atomic partials
__global__ void prep_vec(const float* __restrict__ x,
                         const float* __restrict__ ea_wr, const float* __restrict__ ea_br,
                         const float* __restrict__ ea_wi, const float* __restrict__ ea_bi,
                         const float* __restrict__ eg_wr, const float* __restrict__ eg_br,
                         const float* __restrict__ eg_wi, const float* __restrict__ eg_bi) {
    int tx = threadIdx.x, ty = threadIdx.y;
    int j = blockIdx.x * 32 + tx;
    int k0 = blockIdx.y * 32;
    float sr = 0.f, si = 0.f;
#pragma unroll
    for (int kk = 0; kk < 4; kk++) {
        int k = k0 + ty + kk * 8;
        float xv = x[k];
        int r = k * 512 + j;
        sr += xv * (ea_wr[r] - eg_wr[r]);
        si += xv * (ea_wi[r] - eg_wi[r]);
    }
    __shared__ float shr[8][33], shi[8][33];
    shr[ty][tx] = sr; shi[ty][tx] = si;
    __syncthreads();
    if (ty == 0) {
#pragma unroll
        for (int q = 1; q < 8; q++) { sr += shr[q][tx]; si += shi[q][tx]; }
        if (blockIdx.y == 0) {
            sr += ea_br[j] - ea_bi[j] - eg_br[j] + eg_bi[j];
            si += ea_br[j] + ea_bi[j] - eg_br[j] - eg_bi[j];
        }
        atomicAdd(&g_vre[j], sr);
        atomicAdd(&g_vim[j], si);
    }
}

// eA (fp16 [h_re|h_im]) + h-magnitude columns of cm (cols 513..1536); zeroes g_t
__global__ void prep_eA(const float* __restrict__ h_re, const float* __restrict__ h_im) {
    int idx = blockIdx.x * 256 + threadIdx.x;   // NC * 256 slots (4 dims each)
    if (idx < NC) g_t[idx] = 0.f;
    int n = idx >> 8;
    int k = (idx & 255) * 4;
    float4 a = *reinterpret_cast<const float4*>(h_re + n * 1024 + k);
    float4 b = *reinterpret_cast<const float4*>(h_im + n * 1024 + k);
    __half2 a0; a0.x = __float2half_rn(a.x); a0.y = __float2half_rn(a.y);
    __half2 a1; a1.x = __float2half_rn(a.z); a1.y = __float2half_rn(a.w);
    __half2 b0; b0.x = __float2half_rn(b.x); b0.y = __float2half_rn(b.y);
    __half2 b1; b1.x = __float2half_rn(b.z); b1.y = __float2half_rn(b.w);
    uint2 ua, ub;
    ua.x = *reinterpret_cast<const uint32_t*>(&a0);
    ua.y = *reinterpret_cast<const uint32_t*>(&a1);
    ub.x = *reinterpret_cast<const uint32_t*>(&b0);
    ub.y = *reinterpret_cast<const uint32_t*>(&b1);
    *reinterpret_cast<uint2*>(g_eA + (size_t)n * KENG + k)        = ua;
    *reinterpret_cast<uint2*>(g_eA + (size_t)n * KENG + 1024 + k) = ub;
    size_t cidx = (size_t)n * LDT + 513 + k;
    g_cm[cidx + 0] = __float2half_rn(sqrtf(a.x * a.x + b.x * b.x));
    g_cm[cidx + 1] = __float2half_rn(sqrtf(a.y * a.y + b.y * b.y));
    g_cm[cidx + 2] = __float2half_rn(sqrtf(a.z * a.z + b.z * b.z));
    g_cm[cidx + 3] = __float2half_rn(sqrtf(a.w * a.w + b.w * b.w));
}

__global__ void transpose_e(const float* __restrict__ ea_wr, const float* __restrict__ ea_wi,
                            const float* __restrict__ eg_wr, const float* __restrict__ eg_wi) {
    __shared__ float tr[32][33], ti[32][33];
    int kb = blockIdx.x * 32, nb = blockIdx.y * 32;
    int tx = threadIdx.x, ty = threadIdx.y;
    for (int i = ty; i < 32; i += 8) {
        int k = kb + i, n = nb + tx;
        float re, im;
        if (k < 1024) {
            int r = (512 + k) * 512 + n;
            re = ea_wr[r] - eg_wr[r];
            im = ea_wi[r] - eg_wi[r];
        } else {
            int r = (k - 512) * 512 + n;
            re = -(ea_wi[r] - eg_wi[r]);
            im = ea_wr[r] - eg_wr[r];
        }
        tr[i][tx] = re; ti[i][tx] = im;
    }
    __syncthreads();
    for (int i = ty; i < 32; i += 8) {
        size_t o = (size_t)(nb + i) * KENG + kb + tx;
        g_eB[0][o] = __float2half_rn(tr[tx][i]);
        g_eB[1][o] = __float2half_rn(ti[tx][i]);
    }
}

__global__ void transpose_w(const float* __restrict__ w0, const float* __restrict__ w1,
                            const float* __restrict__ w2, const float* __restrict__ w3) {
    __shared__ float tile[32][33];
    int z = blockIdx.z;
    const float* src = (z == 0) ? w0 : (z == 1) ? w1 : (z == 2) ? w2 : w3;
    int kb = blockIdx.x * 32, nb = blockIdx.y * 32;
    int tx = threadIdx.x, ty = threadIdx.y;
    for (int i = ty; i < 32; i += 8) {
        int k = kb + i;
        tile[i][tx] = (k < GIN) ? src[(size_t)k * 1024 + nb + tx] : 0.f;
    }
    __syncthreads();
    for (int i = ty; i < 32; i += 8) {
        size_t o = (size_t)(nb + i) * LDT + kb + tx;
        g_WT[z][o] = __float2half_rn(tile[tx][i]);
    }
}

// ---------------- mma.sync fp16 GEMM (single-term, cp.async 2-stage) ----------------
#define STAGE_BYTES 32768
#define SMEM_GEMM_BYTES (2 * STAGE_BYTES)
template<int EPI>
__global__ void __launch_bounds__(512, 1) gemm_mma(
    const __half* __restrict__ A0, const __half* __restrict__ A1,
    const __half* __restrict__ B0, const __half* __restrict__ B1,
    int lda, int ldb, int K,
    float* __restrict__ C0, float* __restrict__ C1, int ldc,
    const float* __restrict__ vec0, const float* __restrict__ vec1,
    const float* __restrict__ Zp,
    const float* __restrict__ Hp0, const float* __restrict__ Hp1)
{
    extern __shared__ char smem[];
    uint32_t sb = smem_u32(smem);
    const int z = blockIdx.z;
    const __half* A = z ? A1 : A0;
    const __half* B = z ? B1 : B0;
    float* C = z ? C1 : C0;
    const float* vec = z ? vec1 : vec0;
    const float* Hp = z ? Hp1 : Hp0;

    const int tid = threadIdx.x;
    const int wid = tid >> 5, l = tid & 31;
    const int wm = wid & 3, wn = wid >> 2;
    const int bm = blockIdx.y * 128;
    const int bn = blockIdx.x * 128;

    float acc[2][4][4];
#pragma unroll
    for (int a = 0; a < 2; a++)
#pragma unroll
        for (int b = 0; b < 4; b++)
#pragma unroll
            for (int c = 0; c < 4; c++) acc[a][b][c] = 0.f;

    const int NK = K >> 6;

    auto load_stage = [&](int ch, int stage) {
        const int kc = ch << 6;
        const uint32_t base = sb + (uint32_t)stage * STAGE_BYTES;
#pragma unroll
        for (int j = 0; j < 2; j++) {
            const int within = j * 512 + tid;
            const int row = within >> 3, s = within & 7;
            const uint32_t swz = (uint32_t)((row * 128 + s * 16) ^ ((row & 7) << 4));
            cp16(base + swz,         A + (size_t)(bm + row) * lda + kc + s * 8);
            cp16(base + 16384 + swz, B + (size_t)(bn + row) * ldb + kc + s * 8);
        }
    };

    auto compute = [&](int stage) {
        const uint32_t base = sb + (uint32_t)stage * STAGE_BYTES;
#pragma unroll
        for (int ks = 0; ks < 4; ks++) {
            uint32_t ah[2][4], bhq[2][4];
            const int arow0 = wm * 32 + (l & 15);
            const int akb = ks * 32 + ((l >> 4) << 4);
#pragma unroll
            for (int mi = 0; mi < 2; mi++) {
                int row = arow0 + mi * 16;
                uint32_t ad = base + row * 128 + (akb ^ ((row & 7) << 4));
                ldsm4(ah[mi], ad);
            }
            const int brow0 = wn * 32 + (l & 7) + ((l >> 4) << 3);
            const int bkb = ks * 32 + (((l >> 3) & 1) << 4);
#pragma unroll
            for (int nj = 0; nj < 2; nj++) {
                int row = brow0 + nj * 16;
                uint32_t bd = base + 16384 + row * 128 + (bkb ^ ((row & 7) << 4));
                ldsm4(bhq[nj], bd);
            }
#pragma unroll
            for (int mi = 0; mi < 2; mi++)
#pragma unroll
                for (int ni = 0; ni < 4; ni++) {
                    const uint32_t* b2 = &bhq[ni >> 1][(ni & 1) * 2];
                    mma_f16(acc[mi][ni], ah[mi], b2);
                }
        }
    };

    load_stage(0, 0);
    CP_COMMIT();
    if (NK > 1) load_stage(1, 1);
    CP_COMMIT();

    for (int ch = 0; ch < NK; ch++) {
        CP_WAIT1();
        __syncthreads();
        compute(ch & 1);
        __syncthreads();
        if (ch + 2 < NK) load_stage(ch + 2, ch & 1);
        CP_COMMIT();
    }

    const int mr = bm + wm * 32 + (l >> 2);
    const int nc0 = bn + wn * 32 + ((l & 3) << 1);
    float rs[2][2] = {{0.f, 0.f}, {0.f, 0.f}};
#pragma unroll
    for (int mi = 0; mi < 2; mi++) {
#pragma unroll
        for (int ni = 0; ni < 4; ni++) {
            int n = nc0 + ni * 8;
            float v0 = vec[n], v1 = vec[n + 1];
#pragma unroll
            for (int hh = 0; hh < 2; hh++) {
                int m = mr + mi * 16 + hh * 8;
                float e0 = acc[mi][ni][hh * 2 + 0] + v0;
                float e1 = acc[mi][ni][hh * 2 + 1] + v1;
                if (EPI == 0) rs[mi][hh] += e0 * e0 + e1 * e1;
                if (EPI == 1) {
                    e0 = 1.f / (1.f + expf(-e0));
                    e1 = 1.f / (1.f + expf(-e1));
                }
                if (EPI == 2) {
                    float c0 = tanhf(e0), c1 = tanhf(e1);
                    float z0 = Zp[(size_t)m * ldc + n], z1 = Zp[(size_t)m * ldc + n + 1];
                    float h0 = Hp[(size_t)m * ldc + n], h1 = Hp[(size_t)m * ldc + n + 1];
                    e0 = (1.f - z0) * h0 + z0 * c0;
                    e1 = (1.f - z1) * h1 + z1 * c1;
                }
                float2 o; o.x = e0; o.y = e1;
                *reinterpret_cast<float2*>(C + (size_t)m * ldc + n) = o;
            }
        }
    }
    if (EPI == 0) {
#pragma unroll
        for (int mi = 0; mi < 2; mi++)
#pragma unroll
            for (int hh = 0; hh < 2; hh++) {
                float s = rs[mi][hh];
                s += __shfl_xor_sync(0xffffffffu, s, 1);
                s += __shfl_xor_sync(0xffffffffu, s, 2);
                if ((l & 3) == 0)
                    atomicAdd(&g_t[mr + mi * 16 + hh * 8], s);
            }
    }
}

// ---------------- elementwise / reductions ----------------
__global__ void stats_k(float* __restrict__ out) {
    const float inv512 = 1.f / 512.f;
    int tid = threadIdx.x;
    float t0 = g_t[tid] * inv512, t1 = g_t[tid + 1024] * inv512;
    __shared__ float sh[1024];
    sh[tid] = fmaxf(t0, t1); __syncthreads();
    for (int s = 512; s > 0; s >>= 1) {
        if (tid < s) sh[tid] = fmaxf(sh[tid], sh[tid + s]);
        __syncthreads();
    }
    float mx = sh[0]; __syncthreads();
    sh[tid] = expf(t0 - mx) + expf(t1 - mx); __syncthreads();
    for (int s = 512; s > 0; s >>= 1) {
        if (tid < s) sh[tid] += sh[tid + s];
        __syncthreads();
    }
    float denom = sh[0]; __syncthreads();
    sh[tid] = t0 + t1; __syncthreads();
    for (int s = 512; s > 0; s >>= 1) {
        if (tid < s) sh[tid] += sh[tid + s];
        __syncthreads();
    }
    if (tid == 0) {
        g_stats[0] = mx;
        g_stats[1] = denom;
        out[512] = sh[0] * (1.f / 2048.f);
    }
    g_cv[tid] = 0.f;
}

// o-columns (j<512) of cm/cr/ci + col 512 (t)
__global__ void build_cm(const float* __restrict__ h_re, const float* __restrict__ h_im) {
    int n = blockIdx.x;
    int t = threadIdx.x;   // 256
#pragma unroll
    for (int q = 0; q < 2; q++) {
        int j = t + q * 256;
        size_t idx = (size_t)n * LDT + j;
        float a = g_ore[n * 512 + j], b = g_oim[n * 512 + j];
        g_cr[idx] = __float2half_rn(a);
        g_ci[idx] = __float2half_rn(b);
        g_cm[idx] = __float2half_rn(sqrtf(a * a + b * b));
    }
    if (t == 0) {
        size_t idx = (size_t)n * LDT + 512;
        float v = g_t[n] * (1.f / 512.f);
        __half hv = __float2half_rn(v);
        g_cm[idx] = hv;
        g_cr[idx] = hv;
        g_ci[idx] = __float2half_rn(0.f);
    }
}

// candidate inputs, cols [513, LDT): r*h (and zero padding)
__global__ void build_comb(const float* __restrict__ h_re, const float* __restrict__ h_im) {
    int n = blockIdx.x;
    int tid = threadIdx.x;   // 256
    for (int j = 513 + tid; j < LDT; j += 256) {
        float cr, ci;
        if (j < GIN) {
            int jj = j - 513;
            float rv = g_rr[n * 1024 + jj];
            cr = rv * h_re[n * 1024 + jj];
            ci = rv * h_im[n * 1024 + jj];
        } else { cr = 0.f; ci = 0.f; }
        int idx = n * LDT + j;
        g_cr[idx] = __float2half_rn(cr);
        g_ci[idx] = __float2half_rn(ci);
    }
}

__global__ void fmean1_k() {
    int b = blockIdx.x;
    int comp = b >> 6, f = (b >> 3) & 7, part = b & 7;
    int d = threadIdx.x;
    const float* src = comp ? g_nim : g_nre;
    int r0 = f * 256 + part * 32;
    float s = 0.f;
    for (int i = 0; i < 32; i++) s += src[(r0 + i) * 1024 + d];
    g_fmp[b * 1024 + d] = s;
}

__global__ void fmean2_k() {
    int comp = blockIdx.x, d = threadIdx.x;
    float gsum = 0.f;
    for (int f = 0; f < 8; f++) {
        float s = 0.f;
        for (int part = 0; part < 8; part++)
            s += g_fmp[((comp * 8 + f) * 8 + part) * 1024 + d];
        s *= (1.f / 256.f);
        g_fm[(comp * 8 + f) * 1024 + d] = s;
        gsum += s;
    }
    g_gm[comp * 1024 + d] = gsum * 0.125f;
}

__global__ void apply_sync(float* __restrict__ out, const int* __restrict__ step) {
    int idx = blockIdx.x * 256 + threadIdx.x;
    int comp = idx >> 21;
    int rem = idx & ((1 << 21) - 1);
    int n = rem >> 10, d = rem & 1023;
    const float* src = comp ? g_nim : g_nre;
    float v = src[rem];
    int f = n >> 8;
    v = 0.85f * v + 0.15f * g_fm[(comp * 8 + f) * 1024 + d];
    if (step[0] > 5 && (n & 255) < 64)
        v = 0.85f * v + 0.15f * g_gm[comp * 1024 + d];
    out[513 + idx] = v;
}

__global__ void wsum_k() {
    int blk = blockIdx.x, tid = threadIdx.x;
    const float inv512 = 1.f / 512.f;
    float mx = g_stats[0];
    float inv = 1.f / g_stats[1];
    float a0 = 0.f, a1 = 0.f, a2 = 0.f, a3 = 0.f;
    for (int i = 0; i < 32; i++) {
        int n = blk * 32 + i;
        float w = expf(g_t[n] * inv512 - mx) * inv;
        a0 += w * g_ore[n * 512 + tid];
        a1 += w * g_ore[n * 512 + 256 + tid];
        a2 += w * g_oim[n * 512 + tid];
        a3 += w * g_oim[n * 512 + 256 + tid];
    }
    atomicAdd(&g_cv[tid], a0);
    atomicAdd(&g_cv[256 + tid], a1);
    atomicAdd(&g_cv[512 + tid], a2);
    atomicAdd(&g_cv[768 + tid], a3);
}

__global__ void pred_k(const float* __restrict__ oh_w, const float* __restrict__ oh_b,
                       float* __restrict__ out) {
    int j = blockIdx.x;
    int tid = threadIdx.x;
    float acc = 0.f;
#pragma unroll
    for (int q = 0; q < 4; q++) {
        int k = q * 256 + tid;
        acc += g_cv[k] * oh_w[(size_t)k * 512 + j];
    }
    __shared__ float sh[256];
    sh[tid] = acc; __syncthreads();
    for (int s = 128; s > 0; s >>= 1) {
        if (tid < s) sh[tid] += sh[tid + s];
        __syncthreads();
    }
    if (tid == 0) out[j] = sh[0] + oh_b[j];
}

// ---------------- launch ----------------
extern "C" void kernel_launch(void* const* d_in, const int* in_sizes, int n_in,
                              void* d_out, int out_size) {
    (void)in_sizes; (void)n_in; (void)out_size;
    const float* x     = (const float*)d_in[0];
    const float* h_re  = (const float*)d_in[1];
    const float* h_im  = (const float*)d_in[2];
    const float* ea_wr = (const float*)d_in[3];
    const float* ea_br = (const float*)d_in[4];
    const float* ea_wi = (const float*)d_in[5];
    const float* ea_bi = (const float*)d_in[6];
    const float* eg_wr = (const float*)d_in[7];
    const float* eg_br = (const float*)d_in[8];
    const float* eg_wi = (const float*)d_in[9];
    const float* eg_bi = (const float*)d_in[10];
    const float* gz_w  = (const float*)d_in[11];
    const float* gz_b  = (const float*)d_in[12];
    const float* gr_w  = (const float*)d_in[13];
    const float* gr_b  = (const float*)d_in[14];
    const float* ghr_w = (const float*)d_in[15];
    const float* ghr_b = (const float*)d_in[16];
    const float* ghi_w = (const float*)d_in[17];
    const float* ghi_b = (const float*)d_in[18];
    const float* oh_w  = (const float*)d_in[19];
    const float* oh_b  = (const float*)d_in[20];
    const int*   step  = (const int*)d_in[21];
    float* out = (float*)d_out;

    __half *pEA, *pEB, *pWT, *pCm, *pCr, *pCi;
    float *pVre, *pVim, *pOre, *pOim, *pZ, *pRr, *pNre, *pNim;
    cudaGetSymbolAddress((void**)&pEA,  g_eA);
    cudaGetSymbolAddress((void**)&pEB,  g_eB);
    cudaGetSymbolAddress((void**)&pWT,  g_WT);
    cudaGetSymbolAddress((void**)&pCm,  g_cm);
    cudaGetSymbolAddress((void**)&pCr,  g_cr);
    cudaGetSymbolAddress((void**)&pCi,  g_ci);
    cudaGetSymbolAddress((void**)&pVre, g_vre);
    cudaGetSymbolAddress((void**)&pVim, g_vim);
    cudaGetSymbolAddress((void**)&pOre, g_ore);
    cudaGetSymbolAddress((void**)&pOim, g_oim);
    cudaGetSymbolAddress((void**)&pZ,   g_z);
    cudaGetSymbolAddress((void**)&pRr,  g_rr);
    cudaGetSymbolAddress((void**)&pNre, g_nre);
    cudaGetSymbolAddress((void**)&pNim, g_nim);

    cudaFuncSetAttribute((const void*)gemm_mma<0>, cudaFuncAttributeMaxDynamicSharedMemorySize, SMEM_GEMM_BYTES);
    cudaFuncSetAttribute((const void*)gemm_mma<1>, cudaFuncAttributeMaxDynamicSharedMemorySize, SMEM_GEMM_BYTES);
    cudaFuncSetAttribute((const void*)gemm_mma<2>, cudaFuncAttributeMaxDynamicSharedMemorySize, SMEM_GEMM_BYTES);

    const size_t EB = (size_t)DO * KENG;
    const size_t WB = (size_t)DH * LDT;

    // streams + events created ONCE (first = correctness call, before the
    // harness's pre-capture memory baseline). Reused every call; the enqueued
    // work is identical on each call, and the capture call allocates nothing.
    static cudaStream_t sB = nullptr, sC = nullptr;
    static cudaEvent_t eFork = nullptr, eTe, eTw, ePv, eEng, eC;
    if (sB == nullptr) {
        cudaStreamCreateWithFlags(&sB, cudaStreamNonBlocking);
        cudaStreamCreateWithFlags(&sC, cudaStreamNonBlocking);
        cudaEventCreateWithFlags(&eFork, cudaEventDisableTiming);
        cudaEventCreateWithFlags(&eTe,   cudaEventDisableTiming);
        cudaEventCreateWithFlags(&eTw,   cudaEventDisableTiming);
        cudaEventCreateWithFlags(&ePv,   cudaEventDisableTiming);
        cudaEventCreateWithFlags(&eEng,  cudaEventDisableTiming);
        cudaEventCreateWithFlags(&eC,    cudaEventDisableTiming);
    }

    cudaEventRecord(eFork, 0);
    cudaStreamWaitEvent(sB, eFork, 0);
    cudaStreamWaitEvent(sC, eFork, 0);

    // stream B: engine weight transpose, then GRU weight transpose
    transpose_e<<<dim3(64, 16), dim3(32, 8), 0, sB>>>(ea_wr, ea_wi, eg_wr, eg_wi);
    cudaEventRecord(eTe, sB);
    transpose_w<<<dim3(LDT / 32, 32, 4), dim3(32, 8), 0, sB>>>(gz_w, gr_w, ghr_w, ghi_w);
    cudaEventRecord(eTw, sB);

    // stream C: bias vector
    cudaMemsetAsync(pVre, 0, DO * sizeof(float), sC);
    cudaMemsetAsync(pVim, 0, DO * sizeof(float), sC);
    prep_vec<<<dim3(16, 16), dim3(32, 8), 0, sC>>>(x, ea_wr, ea_br, ea_wi, ea_bi, eg_wr, eg_br, eg_wi, eg_bi);
    cudaEventRecord(ePv, sC);

    // main: activations (also zeroes g_t, writes cm h-mag columns)
    prep_eA<<<2048, 256>>>(h_re, h_im);
    cudaStreamWaitEvent(0, eTe, 0);
    cudaStreamWaitEvent(0, ePv, 0);

    // engine re/im fused (1-term A); epilogue accumulates tension into g_t
    gemm_mma<0><<<dim3(4, 16, 2), 512, SMEM_GEMM_BYTES>>>(
        pEA, pEA, pEB, pEB + EB,
        KENG, KENG, KENG,
        pOre, pOim, 512,
        pVre, pVim, nullptr, nullptr, nullptr);
    cudaEventRecord(eEng, 0);

    // stream C: softmax stats + weighted sum + final projection (parallel to GRU chain)
    cudaStreamWaitEvent(sC, eEng, 0);
    stats_k<<<1, 1024, 0, sC>>>(out);
    wsum_k<<<64, 256, 0, sC>>>();
    pred_k<<<512, 256, 0, sC>>>(oh_w, oh_b, out);
    cudaEventRecord(eC, sC);

    // main: GRU chain
    build_cm<<<NC, 256>>>(h_re, h_im);
    cudaStreamWaitEvent(0, eTw, 0);
    gemm_mma<1><<<dim3(8, 16, 2), 512, SMEM_GEMM_BYTES>>>(
        pCm, pCm, pWT + 0 * WB, pWT + 1 * WB,
        LDT, LDT, LDT,
        pZ, pRr, 1024,
        gz_b, gr_b, nullptr, nullptr, nullptr);

    build_comb<<<NC, 256>>>(h_re, h_im);
    gemm_mma<2><<<dim3(8, 16, 2), 512, SMEM_GEMM_BYTES>>>(
        pCr, pCi, pWT + 2 * WB, pWT + 3 * WB,
        LDT, LDT, LDT,
        pNre, pNim, 1024,
        ghr_b, ghi_b, pZ, h_re, h_im);

    fmean1_k<<<128, 1024>>>();
    fmean2_k<<<2, 1024>>>();
    apply_sync<<<16384, 256>>>(out, step);

    // join stream C
    cudaStreamWaitEvent(0, eC, 0);
}

// round 15
// speedup vs baseline: 1.3126x; 1.0194x over previous
#include <cuda_runtime.h>
#include <cuda_fp16.h>
#include <cstdint>
#include <math.h>

#define NC 2048
#define DH 1024
#define DO 512
#define GIN 1537
#define LDT 1600           // GRU K padded to multiple of 64
#define KENG 2048

// ---------------- scratch ----------------
__device__ __half g_eA[NC * KENG];                        // engine A (single fp16)
__device__ __half g_eB[2][DO * KENG];                     // engine B^T re/im (single fp16)
__device__ __half g_WT[4][DH * LDT];                      // GRU weights^T (single fp16)
__device__ __half g_cm[NC * LDT];                         // GRU gate input
__device__ __half g_cr[NC * LDT];                         // candidate re input
__device__ __half g_ci[NC * LDT];                         // candidate im input
__device__ float g_vre[DO];
__device__ float g_vim[DO];
__device__ float g_ore[NC * DO];
__device__ float g_oim[NC * DO];
__device__ float g_t[NC];                 // raw sum of squares (atomicAdd target)
__device__ float g_stats[2];
__device__ float g_z[NC * DH];
__device__ float g_rr[NC * DH];
__device__ float g_nre[NC * DH];
__device__ float g_nim[NC * DH];
__device__ float g_fmA[2 * 8 * DH];       // faction sums (atomicAdd target)
__device__ float g_fm[2 * 8 * DH];
__device__ float g_gm[2 * DH];
__device__ float g_cv[2 * DO];

// ---------------- helpers ----------------
__device__ __forceinline__ uint32_t smem_u32(const void* p) {
    uint32_t a;
    asm("{ .reg .u64 t; cvta.to.shared.u64 t, %1; cvt.u32.u64 %0, t; }" : "=r"(a) : "l"(p));
    return a;
}
__device__ __forceinline__ void ldsm4(uint32_t* r, uint32_t addr) {
    asm volatile("ldmatrix.sync.aligned.m8n8.x4.shared.b16 {%0,%1,%2,%3}, [%4];"
                 : "=r"(r[0]), "=r"(r[1]), "=r"(r[2]), "=r"(r[3]) : "r"(addr));
}
__device__ __forceinline__ void mma_f16(float* d, const uint32_t* a, const uint32_t* b) {
    asm volatile("mma.sync.aligned.m16n8k16.row.col.f32.f16.f16.f32 "
                 "{%0,%1,%2,%3}, {%4,%5,%6,%7}, {%8,%9}, {%0,%1,%2,%3};"
                 : "+f"(d[0]), "+f"(d[1]), "+f"(d[2]), "+f"(d[3])
                 : "r"(a[0]), "r"(a[1]), "r"(a[2]), "r"(a[3]), "r"(b[0]), "r"(b[1]));
}
__device__ __forceinline__ void cp16(uint32_t dst, const void* src) {
    asm volatile("cp.async.cg.shared.global [%0], [%1], 16;"
                 :: "r"(dst), "l"(__cvta_generic_to_global(src)));
}
#define CP_COMMIT() asm volatile("cp.async.commit_group;" ::: "memory")
#define CP_WAIT1()  asm volatile("cp.async.wait_group 1;" ::: "memory")

// ---------------- prep kernels ----------------
// grid (16 j-groups, 16 k-chunks), block 32x8; coalesced reads + atomic partials
__global__ void prep_vec(const float* __restrict__ x,
                         const float* __restrict__ ea_wr, const float* __restrict__ ea_br,
                         const float* __restrict__ ea_wi, const float* __restrict__ ea_bi,
                         const float* __restrict__ eg_wr, const float* __restrict__ eg_br,
                         const float* __restrict__ eg_wi, const float* __restrict__ eg_bi) {
    int tx = threadIdx.x, ty = threadIdx.y;
    int j = blockIdx.x * 32 + tx;
    int k0 = blockIdx.y * 32;
    float sr = 0.f, si = 0.f;
#pragma unroll
    for (int kk = 0; kk < 4; kk++) {
        int k = k0 + ty + kk * 8;
        float xv = x[k];
        int r = k * 512 + j;
        sr += xv * (ea_wr[r] - eg_wr[r]);
        si += xv * (ea_wi[r] - eg_wi[r]);
    }
    __shared__ float shr[8][33], shi[8][33];
    shr[ty][tx] = sr; shi[ty][tx] = si;
    __syncthreads();
    if (ty == 0) {
#pragma unroll
        for (int q = 1; q < 8; q++) { sr += shr[q][tx]; si += shi[q][tx]; }
        if (blockIdx.y == 0) {
            sr += ea_br[j] - ea_bi[j] - eg_br[j] + eg_bi[j];
            si += ea_br[j] + ea_bi[j] - eg_br[j] - eg_bi[j];
        }
        atomicAdd(&g_vre[j], sr);
        atomicAdd(&g_vim[j], si);
    }
}

// eA (fp16 [h_re|h_im]) + h-magnitude columns of cm (cols 513..1536);
// zeroes g_t and g_fmA
__global__ void prep_eA(const float* __restrict__ h_re, const float* __restrict__ h_im) {
    int idx = blockIdx.x * 256 + threadIdx.x;   // NC * 256 slots (4 dims each)
    if (idx < NC) g_t[idx] = 0.f;
    if (idx < 2 * 8 * DH) g_fmA[idx] = 0.f;
    int n = idx >> 8;
    int k = (idx & 255) * 4;
    float4 a = *reinterpret_cast<const float4*>(h_re + n * 1024 + k);
    float4 b = *reinterpret_cast<const float4*>(h_im + n * 1024 + k);
    __half2 a0; a0.x = __float2half_rn(a.x); a0.y = __float2half_rn(a.y);
    __half2 a1; a1.x = __float2half_rn(a.z); a1.y = __float2half_rn(a.w);
    __half2 b0; b0.x = __float2half_rn(b.x); b0.y = __float2half_rn(b.y);
    __half2 b1; b1.x = __float2half_rn(b.z); b1.y = __float2half_rn(b.w);
    uint2 ua, ub;
    ua.x = *reinterpret_cast<const uint32_t*>(&a0);
    ua.y = *reinterpret_cast<const uint32_t*>(&a1);
    ub.x = *reinterpret_cast<const uint32_t*>(&b0);
    ub.y = *reinterpret_cast<const uint32_t*>(&b1);
    *reinterpret_cast<uint2*>(g_eA + (size_t)n * KENG + k)        = ua;
    *reinterpret_cast<uint2*>(g_eA + (size_t)n * KENG + 1024 + k) = ub;
    size_t cidx = (size_t)n * LDT + 513 + k;
    g_cm[cidx + 0] = __float2half_rn(sqrtf(a.x * a.x + b.x * b.x));
    g_cm[cidx + 1] = __float2half_rn(sqrtf(a.y * a.y + b.y * b.y));
    g_cm[cidx + 2] = __float2half_rn(sqrtf(a.z * a.z + b.z * b.z));
    g_cm[cidx + 3] = __float2half_rn(sqrtf(a.w * a.w + b.w * b.w));
}

__global__ void transpose_e(const float* __restrict__ ea_wr, const float* __restrict__ ea_wi,
                            const float* __restrict__ eg_wr, const float* __restrict__ eg_wi) {
    __shared__ float tr[32][33], ti[32][33];
    int kb = blockIdx.x * 32, nb = blockIdx.y * 32;
    int tx = threadIdx.x, ty = threadIdx.y;
    for (int i = ty; i < 32; i += 8) {
        int k = kb + i, n = nb + tx;
        float re, im;
        if (k < 1024) {
            int r = (512 + k) * 512 + n;
            re = ea_wr[r] - eg_wr[r];
            im = ea_wi[r] - eg_wi[r];
        } else {
            int r = (k - 512) * 512 + n;
            re = -(ea_wi[r] - eg_wi[r]);
            im = ea_wr[r] - eg_wr[r];
        }
        tr[i][tx] = re; ti[i][tx] = im;
    }
    __syncthreads();
    for (int i = ty; i < 32; i += 8) {
        size_t o = (size_t)(nb + i) * KENG + kb + tx;
        g_eB[0][o] = __float2half_rn(tr[tx][i]);
        g_eB[1][o] = __float2half_rn(ti[tx][i]);
    }
}

__global__ void transpose_w(const float* __restrict__ w0, const float* __restrict__ w1,
                            const float* __restrict__ w2, const float* __restrict__ w3) {
    __shared__ float tile[32][33];
    int z = blockIdx.z;
    const float* src = (z == 0) ? w0 : (z == 1) ? w1 : (z == 2) ? w2 : w3;
    int kb = blockIdx.x * 32, nb = blockIdx.y * 32;
    int tx = threadIdx.x, ty = threadIdx.y;
    for (int i = ty; i < 32; i += 8) {
        int k = kb + i;
        tile[i][tx] = (k < GIN) ? src[(size_t)k * 1024 + nb + tx] : 0.f;
    }
    __syncthreads();
    for (int i = ty; i < 32; i += 8) {
        size_t o = (size_t)(nb + i) * LDT + kb + tx;
        g_WT[z][o] = __float2half_rn(tile[tx][i]);
    }
}

// ---------------- mma.sync fp16 GEMM (single-term, cp.async 2-stage) ----------------
#define STAGE_BYTES 32768
#define SMEM_GEMM_BYTES (2 * STAGE_BYTES)
template<int EPI>
__global__ void __launch_bounds__(512, 1) gemm_mma(
    const __half* __restrict__ A0, const __half* __restrict__ A1,
    const __half* __restrict__ B0, const __half* __restrict__ B1,
    int lda, int ldb, int K,
    float* __restrict__ C0, float* __restrict__ C1, int ldc,
    const float* __restrict__ vec0, const float* __restrict__ vec1,
    const float* __restrict__ Zp,
    const float* __restrict__ Hp0, const float* __restrict__ Hp1)
{
    extern __shared__ char smem[];
    uint32_t sb = smem_u32(smem);
    const int z = blockIdx.z;
    const __half* A = z ? A1 : A0;
    const __half* B = z ? B1 : B0;
    float* C = z ? C1 : C0;
    const float* vec = z ? vec1 : vec0;
    const float* Hp = z ? Hp1 : Hp0;

    const int tid = threadIdx.x;
    const int wid = tid >> 5, l = tid & 31;
    const int wm = wid & 3, wn = wid >> 2;
    const int bm = blockIdx.y * 128;
    const int bn = blockIdx.x * 128;

    float acc[2][4][4];
#pragma unroll
    for (int a = 0; a < 2; a++)
#pragma unroll
        for (int b = 0; b < 4; b++)
#pragma unroll
            for (int c = 0; c < 4; c++) acc[a][b][c] = 0.f;

    const int NK = K >> 6;

    auto load_stage = [&](int ch, int stage) {
        const int kc = ch << 6;
        const uint32_t base = sb + (uint32_t)stage * STAGE_BYTES;
#pragma unroll
        for (int j = 0; j < 2; j++) {
            const int within = j * 512 + tid;
            const int row = within >> 3, s = within & 7;
            const uint32_t swz = (uint32_t)((row * 128 + s * 16) ^ ((row & 7) << 4));
            cp16(base + swz,         A + (size_t)(bm + row) * lda + kc + s * 8);
            cp16(base + 16384 + swz, B + (size_t)(bn + row) * ldb + kc + s * 8);
        }
    };

    auto compute = [&](int stage) {
        const uint32_t base = sb + (uint32_t)stage * STAGE_BYTES;
#pragma unroll
        for (int ks = 0; ks < 4; ks++) {
            uint32_t ah[2][4], bhq[2][4];
            const int arow0 = wm * 32 + (l & 15);
            const int akb = ks * 32 + ((l >> 4) << 4);
#pragma unroll
            for (int mi = 0; mi < 2; mi++) {
                int row = arow0 + mi * 16;
                uint32_t ad = base + row * 128 + (akb ^ ((row & 7) << 4));
                ldsm4(ah[mi], ad);
            }
            const int brow0 = wn * 32 + (l & 7) + ((l >> 4) << 3);
            const int bkb = ks * 32 + (((l >> 3) & 1) << 4);
#pragma unroll
            for (int nj = 0; nj < 2; nj++) {
                int row = brow0 + nj * 16;
                uint32_t bd = base + 16384 + row * 128 + (bkb ^ ((row & 7) << 4));
                ldsm4(bhq[nj], bd);
            }
#pragma unroll
            for (int mi = 0; mi < 2; mi++)
#pragma unroll
                for (int ni = 0; ni < 4; ni++) {
                    const uint32_t* b2 = &bhq[ni >> 1][(ni & 1) * 2];
                    mma_f16(acc[mi][ni], ah[mi], b2);
                }
        }
    };

    load_stage(0, 0);
    CP_COMMIT();
    if (NK > 1) load_stage(1, 1);
    CP_COMMIT();

    for (int ch = 0; ch < NK; ch++) {
        CP_WAIT1();
        __syncthreads();
        compute(ch & 1);
        __syncthreads();
        if (ch + 2 < NK) load_stage(ch + 2, ch & 1);
        CP_COMMIT();
    }

    const int mr = bm + wm * 32 + (l >> 2);
    const int nc0 = bn + wn * 32 + ((l & 3) << 1);
    float rs[2][2] = {{0.f, 0.f}, {0.f, 0.f}};   // tension partials (EPI 0)
    float cs[4][2];                               // faction col sums (EPI 2)
    if (EPI == 2) {
#pragma unroll
        for (int a = 0; a < 4; a++) { cs[a][0] = 0.f; cs[a][1] = 0.f; }
    }
#pragma unroll
    for (int mi = 0; mi < 2; mi++) {
#pragma unroll
        for (int ni = 0; ni < 4; ni++) {
            int n = nc0 + ni * 8;
            float v0 = vec[n], v1 = vec[n + 1];
#pragma unroll
            for (int hh = 0; hh < 2; hh++) {
                int m = mr + mi * 16 + hh * 8;
                float e0 = acc[mi][ni][hh * 2 + 0] + v0;
                float e1 = acc[mi][ni][hh * 2 + 1] + v1;
                if (EPI == 0) rs[mi][hh] += e0 * e0 + e1 * e1;
                if (EPI == 1) {
                    e0 = 1.f / (1.f + expf(-e0));
                    e1 = 1.f / (1.f + expf(-e1));
                }
                if (EPI == 2) {
                    float c0 = tanhf(e0), c1 = tanhf(e1);
                    float z0 = Zp[(size_t)m * ldc + n], z1 = Zp[(size_t)m * ldc + n + 1];
                    float h0 = Hp[(size_t)m * ldc + n], h1 = Hp[(size_t)m * ldc + n + 1];
                    e0 = (1.f - z0) * h0 + z0 * c0;
                    e1 = (1.f - z1) * h1 + z1 * c1;
                    cs[ni][0] += e0;
                    cs[ni][1] += e1;
                }
                float2 o; o.x = e0; o.y = e1;
                *reinterpret_cast<float2*>(C + (size_t)m * ldc + n) = o;
            }
        }
    }
    if (EPI == 0) {
#pragma unroll
        for (int mi = 0; mi < 2; mi++)
#pragma unroll
            for (int hh = 0; hh < 2; hh++) {
                float s = rs[mi][hh];
                s += __shfl_xor_sync(0xffffffffu, s, 1);
                s += __shfl_xor_sync(0xffffffffu, s, 2);
                if ((l & 3) == 0)
                    atomicAdd(&g_t[mr + mi * 16 + hh * 8], s);
            }
    }
    if (EPI == 2) {
        const int f = blockIdx.y >> 1;   // 128-row tile lies inside one 256-row faction
#pragma unroll
        for (int ni = 0; ni < 4; ni++)
#pragma unroll
            for (int p = 0; p < 2; p++) {
                float s = cs[ni][p];
                s += __shfl_xor_sync(0xffffffffu, s, 4);
                s += __shfl_xor_sync(0xffffffffu, s, 8);
                s += __shfl_xor_sync(0xffffffffu, s, 16);
                if (l < 4)
                    atomicAdd(&g_fmA[(z * 8 + f) * 1024 + nc0 + ni * 8 + p], s);
            }
    }
}

// ---------------- elementwise / reductions ----------------
__global__ void stats_k(float* __restrict__ out) {
    const float inv512 = 1.f / 512.f;
    int tid = threadIdx.x;
    float t0 = g_t[tid] * inv512, t1 = g_t[tid + 1024] * inv512;
    __shared__ float sh[1024];
    sh[tid] = fmaxf(t0, t1); __syncthreads();
    for (int s = 512; s > 0; s >>= 1) {
        if (tid < s) sh[tid] = fmaxf(sh[tid], sh[tid + s]);
        __syncthreads();
    }
    float mx = sh[0]; __syncthreads();
    sh[tid] = expf(t0 - mx) + expf(t1 - mx); __syncthreads();
    for (int s = 512; s > 0; s >>= 1) {
        if (tid < s) sh[tid] += sh[tid + s];
        __syncthreads();
    }
    float denom = sh[0]; __syncthreads();
    sh[tid] = t0 + t1; __syncthreads();
    for (int s = 512; s > 0; s >>= 1) {
        if (tid < s) sh[tid] += sh[tid + s];
        __syncthreads();
    }
    if (tid == 0) {
        g_stats[0] = mx;
        g_stats[1] = denom;
        out[512] = sh[0] * (1.f / 2048.f);
    }
    g_cv[tid] = 0.f;
}

// o-columns (j<512) of cm/cr/ci + col 512 (t)
__global__ void build_cm(const float* __restrict__ h_re, const float* __restrict__ h_im) {
    int n = blockIdx.x;
    int t = threadIdx.x;   // 256
#pragma unroll
    for (int q = 0; q < 2; q++) {
        int j = t + q * 256;
        size_t idx = (size_t)n * LDT + j;
        float a = g_ore[n * 512 + j], b = g_oim[n * 512 + j];
        g_cr[idx] = __float2half_rn(a);
        g_ci[idx] = __float2half_rn(b);
        g_cm[idx] = __float2half_rn(sqrtf(a * a + b * b));
    }
    if (t == 0) {
        size_t idx = (size_t)n * LDT + 512;
        float v = g_t[n] * (1.f / 512.f);
        __half hv = __float2half_rn(v);
        g_cm[idx] = hv;
        g_cr[idx] = hv;
        g_ci[idx] = __float2half_rn(0.f);
    }
}

// candidate inputs, cols [513, GIN): r*h  (padding cols stay zero from BSS init)
__global__ void build_comb(const float* __restrict__ h_re, const float* __restrict__ h_im) {
    int n = blockIdx.x;
    int tid = threadIdx.x;   // 256
    for (int j = 513 + tid; j < GIN; j += 256) {
        int jj = j - 513;
        float rv = g_rr[n * 1024 + jj];
        float cr = rv * h_re[n * 1024 + jj];
        float ci = rv * h_im[n * 1024 + jj];
        int idx = n * LDT + j;
        g_cr[idx] = __float2half_rn(cr);
        g_ci[idx] = __float2half_rn(ci);
    }
}

// fmean finalize + gmean: 2 blocks (comp), 1024 threads
__global__ void fmean2_k() {
    int comp = blockIdx.x, d = threadIdx.x;
    float gsum = 0.f;
    for (int f = 0; f < 8; f++) {
        float s = g_fmA[(comp * 8 + f) * 1024 + d] * (1.f / 256.f);
        g_fm[(comp * 8 + f) * 1024 + d] = s;
        gsum += s;
    }
    g_gm[comp * 1024 + d] = gsum * 0.125f;
}

__global__ void apply_sync(float* __restrict__ out, const int* __restrict__ step) {
    int idx = blockIdx.x * 256 + threadIdx.x;
    int comp = idx >> 21;
    int rem = idx & ((1 << 21) - 1);
    int n = rem >> 10, d = rem & 1023;
    const float* src = comp ? g_nim : g_nre;
    float v = src[rem];
    int f = n >> 8;
    v = 0.85f * v + 0.15f * g_fm[(comp * 8 + f) * 1024 + d];
    if (step[0] > 5 && (n & 255) < 64)
        v = 0.85f * v + 0.15f * g_gm[comp * 1024 + d];
    out[513 + idx] = v;
}

__global__ void wsum_k() {
    int blk = blockIdx.x, tid = threadIdx.x;
    const float inv512 = 1.f / 512.f;
    float mx = g_stats[0];
    float inv = 1.f / g_stats[1];
    float a0 = 0.f, a1 = 0.f, a2 = 0.f, a3 = 0.f;
    for (int i = 0; i < 32; i++) {
        int n = blk * 32 + i;
        float w = expf(g_t[n] * inv512 - mx) * inv;
        a0 += w * g_ore[n * 512 + tid];
        a1 += w * g_ore[n * 512 + 256 + tid];
        a2 += w * g_oim[n * 512 + tid];
        a3 += w * g_oim[n * 512 + 256 + tid];
    }
    atomicAdd(&g_cv[tid], a0);
    atomicAdd(&g_cv[256 + tid], a1);
    atomicAdd(&g_cv[512 + tid], a2);
    atomicAdd(&g_cv[768 + tid], a3);
}

__global__ void pred_k(const float* __restrict__ oh_w, const float* __restrict__ oh_b,
                       float* __restrict__ out) {
    int j = blockIdx.x;
    int tid = threadIdx.x;
    float acc = 0.f;
#pragma unroll
    for (int q = 0; q < 4; q++) {
        int k = q * 256 + tid;
        acc += g_cv[k] * oh_w[(size_t)k * 512 + j];
    }
    __shared__ float sh[256];
    sh[tid] = acc; __syncthreads();
    for (int s = 128; s > 0; s >>= 1) {
        if (tid < s) sh[tid] += sh[tid + s];
        __syncthreads();
    }
    if (tid == 0) out[j] = sh[0] + oh_b[j];
}

// ---------------- launch ----------------
extern "C" void kernel_launch(void* const* d_in, const int* in_sizes, int n_in,
                              void* d_out, int out_size) {
    (void)in_sizes; (void)n_in; (void)out_size;
    const float* x     = (const float*)d_in[0];
    const float* h_re  = (const float*)d_in[1];
    const float* h_im  = (const float*)d_in[2];
    const float* ea_wr = (const float*)d_in[3];
    const float* ea_br = (const float*)d_in[4];
    const float* ea_wi = (const float*)d_in[5];
    const float* ea_bi = (const float*)d_in[6];
    const float* eg_wr = (const float*)d_in[7];
    const float* eg_br = (const float*)d_in[8];
    const float* eg_wi = (const float*)d_in[9];
    const float* eg_bi = (const float*)d_in[10];
    const float* gz_w  = (const float*)d_in[11];
    const float* gz_b  = (const float*)d_in[12];
    const float* gr_w  = (const float*)d_in[13];
    const float* gr_b  = (const float*)d_in[14];
    const float* ghr_w = (const float*)d_in[15];
    const float* ghr_b = (const float*)d_in[16];
    const float* ghi_w = (const float*)d_in[17];
    const float* ghi_b = (const float*)d_in[18];
    const float* oh_w  = (const float*)d_in[19];
    const float* oh_b  = (const float*)d_in[20];
    const int*   step  = (const int*)d_in[21];
    float* out = (float*)d_out;

    __half *pEA, *pEB, *pWT, *pCm, *pCr, *pCi;
    float *pVre, *pVim, *pOre, *pOim, *pZ, *pRr, *pNre, *pNim;
    cudaGetSymbolAddress((void**)&pEA,  g_eA);
    cudaGetSymbolAddress((void**)&pEB,  g_eB);
    cudaGetSymbolAddress((void**)&pWT,  g_WT);
    cudaGetSymbolAddress((void**)&pCm,  g_cm);
    cudaGetSymbolAddress((void**)&pCr,  g_cr);
    cudaGetSymbolAddress((void**)&pCi,  g_ci);
    cudaGetSymbolAddress((void**)&pVre, g_vre);
    cudaGetSymbolAddress((void**)&pVim, g_vim);
    cudaGetSymbolAddress((void**)&pOre, g_ore);
    cudaGetSymbolAddress((void**)&pOim, g_oim);
    cudaGetSymbolAddress((void**)&pZ,   g_z);
    cudaGetSymbolAddress((void**)&pRr,  g_rr);
    cudaGetSymbolAddress((void**)&pNre, g_nre);
    cudaGetSymbolAddress((void**)&pNim, g_nim);

    cudaFuncSetAttribute((const void*)gemm_mma<0>, cudaFuncAttributeMaxDynamicSharedMemorySize, SMEM_GEMM_BYTES);
    cudaFuncSetAttribute((const void*)gemm_mma<1>, cudaFuncAttributeMaxDynamicSharedMemorySize, SMEM_GEMM_BYTES);
    cudaFuncSetAttribute((const void*)gemm_mma<2>, cudaFuncAttributeMaxDynamicSharedMemorySize, SMEM_GEMM_BYTES);

    const size_t EB = (size_t)DO * KENG;
    const size_t WB = (size_t)DH * LDT;

    // streams + events created ONCE (first = correctness call, before the
    // harness's pre-capture memory baseline). Reused every call; the enqueued
    // work is identical on each call, and the capture call allocates nothing.
    static cudaStream_t sB = nullptr, sC = nullptr;
    static cudaEvent_t eFork = nullptr, eTe, eTw, ePv, eEng, eC;
    if (sB == nullptr) {
        cudaStreamCreateWithFlags(&sB, cudaStreamNonBlocking);
        cudaStreamCreateWithFlags(&sC, cudaStreamNonBlocking);
        cudaEventCreateWithFlags(&eFork, cudaEventDisableTiming);
        cudaEventCreateWithFlags(&eTe,   cudaEventDisableTiming);
        cudaEventCreateWithFlags(&eTw,   cudaEventDisableTiming);
        cudaEventCreateWithFlags(&ePv,   cudaEventDisableTiming);
        cudaEventCreateWithFlags(&eEng,  cudaEventDisableTiming);
        cudaEventCreateWithFlags(&eC,    cudaEventDisableTiming);
    }

    cudaEventRecord(eFork, 0);
    cudaStreamWaitEvent(sB, eFork, 0);
    cudaStreamWaitEvent(sC, eFork, 0);

    // stream B: engine weight transpose, then GRU weight transpose
    transpose_e<<<dim3(64, 16), dim3(32, 8), 0, sB>>>(ea_wr, ea_wi, eg_wr, eg_wi);
    cudaEventRecord(eTe, sB);
    transpose_w<<<dim3(LDT / 32, 32, 4), dim3(32, 8), 0, sB>>>(gz_w, gr_w, ghr_w, ghi_w);
    cudaEventRecord(eTw, sB);

    // stream C: bias vector
    cudaMemsetAsync(pVre, 0, DO * sizeof(float), sC);
    cudaMemsetAsync(pVim, 0, DO * sizeof(float), sC);
    prep_vec<<<dim3(16, 16), dim3(32, 8), 0, sC>>>(x, ea_wr, ea_br, ea_wi, ea_bi, eg_wr, eg_br, eg_wi, eg_bi);
    cudaEventRecord(ePv, sC);

    // main: activations (also zeroes g_t/g_fmA, writes cm h-mag columns)
    prep_eA<<<2048, 256>>>(h_re, h_im);
    cudaStreamWaitEvent(0, eTe, 0);
    cudaStreamWaitEvent(0, ePv, 0);

    // engine re/im fused (1-term A); epilogue accumulates tension into g_t
    gemm_mma<0><<<dim3(4, 16, 2), 512, SMEM_GEMM_BYTES>>>(
        pEA, pEA, pEB, pEB + EB,
        KENG, KENG, KENG,
        pOre, pOim, 512,
        pVre, pVim, nullptr, nullptr, nullptr);
    cudaEventRecord(eEng, 0);

    // stream C: softmax stats + weighted sum + final projection (parallel to GRU chain)
    cudaStreamWaitEvent(sC, eEng, 0);
    stats_k<<<1, 1024, 0, sC>>>(out);
    wsum_k<<<64, 256, 0, sC>>>();
    pred_k<<<512, 256, 0, sC>>>(oh_w, oh_b, out);
    cudaEventRecord(eC, sC);

    // main: GRU chain
    build_cm<<<NC, 256>>>(h_re, h_im);
    cudaStreamWaitEvent(0, eTw, 0);
    gemm_mma<1><<<dim3(8, 16, 2), 512, SMEM_GEMM_BYTES>>>(
        pCm, pCm, pWT + 0 * WB, pWT + 1 * WB,
        LDT, LDT, LDT,
        pZ, pRr, 1024,
        gz_b, gr_b, nullptr, nullptr, nullptr);

    build_comb<<<NC, 256>>>(h_re, h_im);
    // candidates: epilogue accumulates faction sums into g_fmA
    gemm_mma<2><<<dim3(8, 16, 2), 512, SMEM_GEMM_BYTES>>>(
        pCr, pCi, pWT + 2 * WB, pWT + 3 * WB,
        LDT, LDT, LDT,
        pNre, pNim, 1024,
        ghr_b, ghi_b, pZ, h_re, h_im);

    fmean2_k<<<2, 1024>>>();
    apply_sync<<<16384, 256>>>(out, step);

    // join stream C
    cudaStreamWaitEvent(0, eC, 0);
}

// round 16
// speedup vs baseline: 1.3741x; 1.0469x over previous
#include <cuda_runtime.h>
#include <cuda_fp16.h>
#include <cstdint>
#include <math.h>

#define NC 2048
#define DH 1024
#define DO 512
#define GIN 1537
#define LDT 1600           // GRU K padded to multiple of 64
#define KENG 2048

// ---------------- scratch ----------------
__device__ __half g_eA[NC * KENG];                        // engine A (single fp16)
__device__ __half g_eB[2][DO * KENG];                     // engine B^T re/im (single fp16)
__device__ __half g_WT[4][DH * LDT];                      // GRU weights^T (single fp16)
__device__ __half g_cm[NC * LDT];                         // GRU gate input
__device__ __half g_cr[NC * LDT];                         // candidate re input
__device__ __half g_ci[NC * LDT];                         // candidate im input
__device__ float g_vre[DO];
__device__ float g_vim[DO];
__device__ float g_ore[NC * DO];
__device__ float g_oim[NC * DO];
__device__ float g_t[NC];                 // raw sum of squares (atomicAdd target)
__device__ float g_stats[2];
__device__ float g_z[NC * DH];
__device__ float g_rr[NC * DH];
__device__ float g_nre[NC * DH];
__device__ float g_nim[NC * DH];
__device__ float g_fmA[2 * 8 * DH];       // faction sums (atomicAdd target)
__device__ float g_fm[2 * 8 * DH];
__device__ float g_gm[2 * DH];
__device__ float g_cv[2 * DO];

// ---------------- helpers ----------------
__device__ __forceinline__ uint32_t smem_u32(const void* p) {
    uint32_t a;
    asm("{ .reg .u64 t; cvta.to.shared.u64 t, %1; cvt.u32.u64 %0, t; }" : "=r"(a) : "l"(p));
    return a;
}
__device__ __forceinline__ void ldsm4(uint32_t* r, uint32_t addr) {
    asm volatile("ldmatrix.sync.aligned.m8n8.x4.shared.b16 {%0,%1,%2,%3}, [%4];"
                 : "=r"(r[0]), "=r"(r[1]), "=r"(r[2]), "=r"(r[3]) : "r"(addr));
}
__device__ __forceinline__ void mma_f16(float* d, const uint32_t* a, const uint32_t* b) {
    asm volatile("mma.sync.aligned.m16n8k16.row.col.f32.f16.f16.f32 "
                 "{%0,%1,%2,%3}, {%4,%5,%6,%7}, {%8,%9}, {%0,%1,%2,%3};"
                 : "+f"(d[0]), "+f"(d[1]), "+f"(d[2]), "+f"(d[3])
                 : "r"(a[0]), "r"(a[1]), "r"(a[2]), "r"(a[3]), "r"(b[0]), "r"(b[1]));
}
__device__ __forceinline__ void cp16(uint32_t dst, const void* src) {
    asm volatile("cp.async.cg.shared.global [%0], [%1], 16;"
                 :: "r"(dst), "l"(__cvta_generic_to_global(src)));
}
#define CP_COMMIT() asm volatile("cp.async.commit_group;" ::: "memory")
#define CP_WAIT1()  asm volatile("cp.async.wait_group 1;" ::: "memory")

// ---------------- prep kernels ----------------
__global__ void prep_vec(const float* __restrict__ x,
                         const float* __restrict__ ea_wr, const float* __restrict__ ea_br,
                         const float* __restrict__ ea_wi, const float* __restrict__ ea_bi,
                         const float* __restrict__ eg_wr, const float* __restrict__ eg_br,
                         const float* __restrict__ eg_wi, const float* __restrict__ eg_bi) {
    int tx = threadIdx.x, ty = threadIdx.y;
    int j = blockIdx.x * 32 + tx;
    int k0 = blockIdx.y * 32;
    float sr = 0.f, si = 0.f;
#pragma unroll
    for (int kk = 0; kk < 4; kk++) {
        int k = k0 + ty + kk * 8;
        float xv = x[k];
        int r = k * 512 + j;
        sr += xv * (ea_wr[r] - eg_wr[r]);
        si += xv * (ea_wi[r] - eg_wi[r]);
    }
    __shared__ float shr[8][33], shi[8][33];
    shr[ty][tx] = sr; shi[ty][tx] = si;
    __syncthreads();
    if (ty == 0) {
#pragma unroll
        for (int q = 1; q < 8; q++) { sr += shr[q][tx]; si += shi[q][tx]; }
        if (blockIdx.y == 0) {
            sr += ea_br[j] - ea_bi[j] - eg_br[j] + eg_bi[j];
            si += ea_br[j] + ea_bi[j] - eg_br[j] - eg_bi[j];
        }
        atomicAdd(&g_vre[j], sr);
        atomicAdd(&g_vim[j], si);
    }
}

// eA (fp16 [h_re|h_im]) + h-magnitude columns of cm (cols 513..1536);
// zeroes g_t and g_fmA
__global__ void prep_eA(const float* __restrict__ h_re, const float* __restrict__ h_im) {
    int idx = blockIdx.x * 256 + threadIdx.x;   // NC * 256 slots (4 dims each)
    if (idx < NC) g_t[idx] = 0.f;
    if (idx < 2 * 8 * DH) g_fmA[idx] = 0.f;
    int n = idx >> 8;
    int k = (idx & 255) * 4;
    float4 a = *reinterpret_cast<const float4*>(h_re + n * 1024 + k);
    float4 b = *reinterpret_cast<const float4*>(h_im + n * 1024 + k);
    __half2 a0; a0.x = __float2half_rn(a.x); a0.y = __float2half_rn(a.y);
    __half2 a1; a1.x = __float2half_rn(a.z); a1.y = __float2half_rn(a.w);
    __half2 b0; b0.x = __float2half_rn(b.x); b0.y = __float2half_rn(b.y);
    __half2 b1; b1.x = __float2half_rn(b.z); b1.y = __float2half_rn(b.w);
    uint2 ua, ub;
    ua.x = *reinterpret_cast<const uint32_t*>(&a0);
    ua.y = *reinterpret_cast<const uint32_t*>(&a1);
    ub.x = *reinterpret_cast<const uint32_t*>(&b0);
    ub.y = *reinterpret_cast<const uint32_t*>(&b1);
    *reinterpret_cast<uint2*>(g_eA + (size_t)n * KENG + k)        = ua;
    *reinterpret_cast<uint2*>(g_eA + (size_t)n * KENG + 1024 + k) = ub;
    size_t cidx = (size_t)n * LDT + 513 + k;
    g_cm[cidx + 0] = __float2half_rn(sqrtf(a.x * a.x + b.x * b.x));
    g_cm[cidx + 1] = __float2half_rn(sqrtf(a.y * a.y + b.y * b.y));
    g_cm[cidx + 2] = __float2half_rn(sqrtf(a.z * a.z + b.z * b.z));
    g_cm[cidx + 3] = __float2half_rn(sqrtf(a.w * a.w + b.w * b.w));
}

__global__ void transpose_e(const float* __restrict__ ea_wr, const float* __restrict__ ea_wi,
                            const float* __restrict__ eg_wr, const float* __restrict__ eg_wi) {
    __shared__ float tr[32][33], ti[32][33];
    int kb = blockIdx.x * 32, nb = blockIdx.y * 32;
    int tx = threadIdx.x, ty = threadIdx.y;
    for (int i = ty; i < 32; i += 8) {
        int k = kb + i, n = nb + tx;
        float re, im;
        if (k < 1024) {
            int r = (512 + k) * 512 + n;
            re = ea_wr[r] - eg_wr[r];
            im = ea_wi[r] - eg_wi[r];
        } else {
            int r = (k - 512) * 512 + n;
            re = -(ea_wi[r] - eg_wi[r]);
            im = ea_wr[r] - eg_wr[r];
        }
        tr[i][tx] = re; ti[i][tx] = im;
    }
    __syncthreads();
    for (int i = ty; i < 32; i += 8) {
        size_t o = (size_t)(nb + i) * KENG + kb + tx;
        g_eB[0][o] = __float2half_rn(tr[tx][i]);
        g_eB[1][o] = __float2half_rn(ti[tx][i]);
    }
}

__global__ void transpose_w(const float* __restrict__ w0, const float* __restrict__ w1,
                            const float* __restrict__ w2, const float* __restrict__ w3) {
    __shared__ float tile[32][33];
    int z = blockIdx.z;
    const float* src = (z == 0) ? w0 : (z == 1) ? w1 : (z == 2) ? w2 : w3;
    int kb = blockIdx.x * 32, nb = blockIdx.y * 32;
    int tx = threadIdx.x, ty = threadIdx.y;
    for (int i = ty; i < 32; i += 8) {
        int k = kb + i;
        tile[i][tx] = (k < GIN) ? src[(size_t)k * 1024 + nb + tx] : 0.f;
    }
    __syncthreads();
    for (int i = ty; i < 32; i += 8) {
        size_t o = (size_t)(nb + i) * LDT + kb + tx;
        g_WT[z][o] = __float2half_rn(tile[tx][i]);
    }
}

// ---------------- mma.sync fp16 GEMM (single-term, cp.async 2-stage) ----------------
// MT = M-tile rows (128 or 256); 16 warps (4x4), 512 threads, 1 CTA/SM.
// stage layout: A@0 (128*MROWS bytes/row-block), B after A.
template<int EPI, int MROWS>   // MROWS = MT/128
__global__ void __launch_bounds__(512, 1) gemm_mma(
    const __half* __restrict__ A0, const __half* __restrict__ A1,
    const __half* __restrict__ B0, const __half* __restrict__ B1,
    int lda, int ldb, int K,
    float* __restrict__ C0, float* __restrict__ C1, int ldc,
    const float* __restrict__ vec0, const float* __restrict__ vec1,
    const float* __restrict__ Zp,
    const float* __restrict__ Hp0, const float* __restrict__ Hp1)
{
    constexpr uint32_t ABYTES = 16384u * MROWS;
    constexpr uint32_t STG = ABYTES + 16384u;
    extern __shared__ char smem[];
    uint32_t sb = smem_u32(smem);
    const int z = blockIdx.z;
    const __half* A = z ? A1 : A0;
    const __half* B = z ? B1 : B0;
    float* C = z ? C1 : C0;
    const float* vec = z ? vec1 : vec0;
    const float* Hp = z ? Hp1 : Hp0;

    const int tid = threadIdx.x;
    const int wid = tid >> 5, l = tid & 31;
    const int wm = wid & 3, wn = wid >> 2;
    const int bm = blockIdx.y * (128 * MROWS);
    const int bn = blockIdx.x * 128;

    float acc[2 * MROWS][4][4];
#pragma unroll
    for (int a = 0; a < 2 * MROWS; a++)
#pragma unroll
        for (int b = 0; b < 4; b++)
#pragma unroll
            for (int c = 0; c < 4; c++) acc[a][b][c] = 0.f;

    const int NK = K >> 6;

    auto load_stage = [&](int ch, int stage) {
        const int kc = ch << 6;
        const uint32_t base = sb + (uint32_t)stage * STG;
#pragma unroll
        for (int j = 0; j < 2 * MROWS; j++) {   // A rows
            const int within = j * 512 + tid;
            const int row = within >> 3, s = within & 7;
            const uint32_t swz = (uint32_t)((row * 128 + s * 16) ^ ((row & 7) << 4));
            cp16(base + swz, A + (size_t)(bm + row) * lda + kc + s * 8);
        }
#pragma unroll
        for (int j = 0; j < 2; j++) {           // B rows
            const int within = j * 512 + tid;
            const int row = within >> 3, s = within & 7;
            const uint32_t swz = (uint32_t)((row * 128 + s * 16) ^ ((row & 7) << 4));
            cp16(base + ABYTES + swz, B + (size_t)(bn + row) * ldb + kc + s * 8);
        }
    };

    auto compute = [&](int stage) {
        const uint32_t base = sb + (uint32_t)stage * STG;
#pragma unroll
        for (int ks = 0; ks < 4; ks++) {
            uint32_t ah[2 * MROWS][4], bhq[2][4];
            const int arow0 = wm * (32 * MROWS) + (l & 15);
            const int akb = ks * 32 + ((l >> 4) << 4);
#pragma unroll
            for (int mi = 0; mi < 2 * MROWS; mi++) {
                int row = arow0 + mi * 16;
                uint32_t ad = base + row * 128 + (akb ^ ((row & 7) << 4));
                ldsm4(ah[mi], ad);
            }
            const int brow0 = wn * 32 + (l & 7) + ((l >> 4) << 3);
            const int bkb = ks * 32 + (((l >> 3) & 1) << 4);
#pragma unroll
            for (int nj = 0; nj < 2; nj++) {
                int row = brow0 + nj * 16;
                uint32_t bd = base + ABYTES + row * 128 + (bkb ^ ((row & 7) << 4));
                ldsm4(bhq[nj], bd);
            }
#pragma unroll
            for (int mi = 0; mi < 2 * MROWS; mi++)
#pragma unroll
                for (int ni = 0; ni < 4; ni++) {
                    const uint32_t* b2 = &bhq[ni >> 1][(ni & 1) * 2];
                    mma_f16(acc[mi][ni], ah[mi], b2);
                }
        }
    };

    load_stage(0, 0);
    CP_COMMIT();
    if (NK > 1) load_stage(1, 1);
    CP_COMMIT();

    for (int ch = 0; ch < NK; ch++) {
        CP_WAIT1();
        __syncthreads();
        compute(ch & 1);
        __syncthreads();
        if (ch + 2 < NK) load_stage(ch + 2, ch & 1);
        CP_COMMIT();
    }

    const int mr = bm + wm * (32 * MROWS) + (l >> 2);
    const int nc0 = bn + wn * 32 + ((l & 3) << 1);
    float rs[2 * MROWS][2];
    float cs[4][2];
#pragma unroll
    for (int a = 0; a < 2 * MROWS; a++) { rs[a][0] = 0.f; rs[a][1] = 0.f; }
    if (EPI == 2) {
#pragma unroll
        for (int a = 0; a < 4; a++) { cs[a][0] = 0.f; cs[a][1] = 0.f; }
    }
#pragma unroll
    for (int mi = 0; mi < 2 * MROWS; mi++) {
#pragma unroll
        for (int ni = 0; ni < 4; ni++) {
            int n = nc0 + ni * 8;
            float v0 = vec[n], v1 = vec[n + 1];
#pragma unroll
            for (int hh = 0; hh < 2; hh++) {
                int m = mr + mi * 16 + hh * 8;
                float e0 = acc[mi][ni][hh * 2 + 0] + v0;
                float e1 = acc[mi][ni][hh * 2 + 1] + v1;
                if (EPI == 0) rs[mi][hh] += e0 * e0 + e1 * e1;
                if (EPI == 1) {
                    e0 = 1.f / (1.f + expf(-e0));
                    e1 = 1.f / (1.f + expf(-e1));
                }
                if (EPI == 2) {
                    float c0 = tanhf(e0), c1 = tanhf(e1);
                    float z0 = Zp[(size_t)m * ldc + n], z1 = Zp[(size_t)m * ldc + n + 1];
                    float h0 = Hp[(size_t)m * ldc + n], h1 = Hp[(size_t)m * ldc + n + 1];
                    e0 = (1.f - z0) * h0 + z0 * c0;
                    e1 = (1.f - z1) * h1 + z1 * c1;
                    cs[ni][0] += e0;
                    cs[ni][1] += e1;
                }
                float2 o; o.x = e0; o.y = e1;
                *reinterpret_cast<float2*>(C + (size_t)m * ldc + n) = o;
            }
        }
    }
    if (EPI == 0) {
#pragma unroll
        for (int mi = 0; mi < 2 * MROWS; mi++)
#pragma unroll
            for (int hh = 0; hh < 2; hh++) {
                float s = rs[mi][hh];
                s += __shfl_xor_sync(0xffffffffu, s, 1);
                s += __shfl_xor_sync(0xffffffffu, s, 2);
                if ((l & 3) == 0)
                    atomicAdd(&g_t[mr + mi * 16 + hh * 8], s);
            }
    }
    if (EPI == 2) {
        const int f = bm >> 8;   // CTA tile lies inside one 256-row faction
#pragma unroll
        for (int ni = 0; ni < 4; ni++)
#pragma unroll
            for (int p = 0; p < 2; p++) {
                float s = cs[ni][p];
                s += __shfl_xor_sync(0xffffffffu, s, 4);
                s += __shfl_xor_sync(0xffffffffu, s, 8);
                s += __shfl_xor_sync(0xffffffffu, s, 16);
                if (l < 4)
                    atomicAdd(&g_fmA[(z * 8 + f) * 1024 + nc0 + ni * 8 + p], s);
            }
    }
}

// ---------------- elementwise / reductions ----------------
__global__ void stats_k(float* __restrict__ out) {
    const float inv512 = 1.f / 512.f;
    int tid = threadIdx.x;
    float t0 = g_t[tid] * inv512, t1 = g_t[tid + 1024] * inv512;
    __shared__ float sh[1024];
    sh[tid] = fmaxf(t0, t1); __syncthreads();
    for (int s = 512; s > 0; s >>= 1) {
        if (tid < s) sh[tid] = fmaxf(sh[tid], sh[tid + s]);
        __syncthreads();
    }
    float mx = sh[0]; __syncthreads();
    sh[tid] = expf(t0 - mx) + expf(t1 - mx); __syncthreads();
    for (int s = 512; s > 0; s >>= 1) {
        if (tid < s) sh[tid] += sh[tid + s];
        __syncthreads();
    }
    float denom = sh[0]; __syncthreads();
    sh[tid] = t0 + t1; __syncthreads();
    for (int s = 512; s > 0; s >>= 1) {
        if (tid < s) sh[tid] += sh[tid + s];
        __syncthreads();
    }
    if (tid == 0) {
        g_stats[0] = mx;
        g_stats[1] = denom;
        out[512] = sh[0] * (1.f / 2048.f);
    }
    g_cv[tid] = 0.f;
}

// o-columns (j<512) of cm/cr/ci + col 512 (t)
__global__ void build_cm(const float* __restrict__ h_re, const float* __restrict__ h_im) {
    int n = blockIdx.x;
    int t = threadIdx.x;   // 256
#pragma unroll
    for (int q = 0; q < 2; q++) {
        int j = t + q * 256;
        size_t idx = (size_t)n * LDT + j;
        float a = g_ore[n * 512 + j], b = g_oim[n * 512 + j];
        g_cr[idx] = __float2half_rn(a);
        g_ci[idx] = __float2half_rn(b);
        g_cm[idx] = __float2half_rn(sqrtf(a * a + b * b));
    }
    if (t == 0) {
        size_t idx = (size_t)n * LDT + 512;
        float v = g_t[n] * (1.f / 512.f);
        __half hv = __float2half_rn(v);
        g_cm[idx] = hv;
        g_cr[idx] = hv;
        g_ci[idx] = __float2half_rn(0.f);
    }
}

// candidate inputs, cols [513, GIN): r*h  (padding cols stay zero from BSS init)
__global__ void build_comb(const float* __restrict__ h_re, const float* __restrict__ h_im) {
    int n = blockIdx.x;
    int tid = threadIdx.x;   // 256
    for (int j = 513 + tid; j < GIN; j += 256) {
        int jj = j - 513;
        float rv = g_rr[n * 1024 + jj];
        float cr = rv * h_re[n * 1024 + jj];
        float ci = rv * h_im[n * 1024 + jj];
        int idx = n * LDT + j;
        g_cr[idx] = __float2half_rn(cr);
        g_ci[idx] = __float2half_rn(ci);
    }
}

// fmean finalize + gmean: 2 blocks (comp), 1024 threads
__global__ void fmean2_k() {
    int comp = blockIdx.x, d = threadIdx.x;
    float gsum = 0.f;
    for (int f = 0; f < 8; f++) {
        float s = g_fmA[(comp * 8 + f) * 1024 + d] * (1.f / 256.f);
        g_fm[(comp * 8 + f) * 1024 + d] = s;
        gsum += s;
    }
    g_gm[comp * 1024 + d] = gsum * 0.125f;
}

__global__ void apply_sync(float* __restrict__ out, const int* __restrict__ step) {
    int idx = blockIdx.x * 256 + threadIdx.x;
    int comp = idx >> 21;
    int rem = idx & ((1 << 21) - 1);
    int n = rem >> 10, d = rem & 1023;
    const float* src = comp ? g_nim : g_nre;
    float v = src[rem];
    int f = n >> 8;
    v = 0.85f * v + 0.15f * g_fm[(comp * 8 + f) * 1024 + d];
    if (step[0] > 5 && (n & 255) < 64)
        v = 0.85f * v + 0.15f * g_gm[comp * 1024 + d];
    out[513 + idx] = v;
}

__global__ void wsum_k() {
    int blk = blockIdx.x, tid = threadIdx.x;
    const float inv512 = 1.f / 512.f;
    float mx = g_stats[0];
    float inv = 1.f / g_stats[1];
    float a0 = 0.f, a1 = 0.f, a2 = 0.f, a3 = 0.f;
    for (int i = 0; i < 32; i++) {
        int n = blk * 32 + i;
        float w = expf(g_t[n] * inv512 - mx) * inv;
        a0 += w * g_ore[n * 512 + tid];
        a1 += w * g_ore[n * 512 + 256 + tid];
        a2 += w * g_oim[n * 512 + tid];
        a3 += w * g_oim[n * 512 + 256 + tid];
    }
    atomicAdd(&g_cv[tid], a0);
    atomicAdd(&g_cv[256 + tid], a1);
    atomicAdd(&g_cv[512 + tid], a2);
    atomicAdd(&g_cv[768 + tid], a3);
}

__global__ void pred_k(const float* __restrict__ oh_w, const float* __restrict__ oh_b,
                       float* __restrict__ out) {
    int j = blockIdx.x;
    int tid = threadIdx.x;
    float acc = 0.f;
#pragma unroll
    for (int q = 0; q < 4; q++) {
        int k = q * 256 + tid;
        acc += g_cv[k] * oh_w[(size_t)k * 512 + j];
    }
    __shared__ float sh[256];
    sh[tid] = acc; __syncthreads();
    for (int s = 128; s > 0; s >>= 1) {
        if (tid < s) sh[tid] += sh[tid + s];
        __syncthreads();
    }
    if (tid == 0) out[j] = sh[0] + oh_b[j];
}

// ---------------- launch ----------------
extern "C" void kernel_launch(void* const* d_in, const int* in_sizes, int n_in,
                              void* d_out, int out_size) {
    (void)in_sizes; (void)n_in; (void)out_size;
    const float* x     = (const float*)d_in[0];
    const float* h_re  = (const float*)d_in[1];
    const float* h_im  = (const float*)d_in[2];
    const float* ea_wr = (const float*)d_in[3];
    const float* ea_br = (const float*)d_in[4];
    const float* ea_wi = (const float*)d_in[5];
    const float* ea_bi = (const float*)d_in[6];
    const float* eg_wr = (const float*)d_in[7];
    const float* eg_br = (const float*)d_in[8];
    const float* eg_wi = (const float*)d_in[9];
    const float* eg_bi = (const float*)d_in[10];
    const float* gz_w  = (const float*)d_in[11];
    const float* gz_b  = (const float*)d_in[12];
    const float* gr_w  = (const float*)d_in[13];
    const float* gr_b  = (const float*)d_in[14];
    const float* ghr_w = (const float*)d_in[15];
    const float* ghr_b = (const float*)d_in[16];
    const float* ghi_w = (const float*)d_in[17];
    const float* ghi_b = (const float*)d_in[18];
    const float* oh_w  = (const float*)d_in[19];
    const float* oh_b  = (const float*)d_in[20];
    const int*   step  = (const int*)d_in[21];
    float* out = (float*)d_out;

    __half *pEA, *pEB, *pWT, *pCm, *pCr, *pCi;
    float *pVre, *pVim, *pOre, *pOim, *pZ, *pRr, *pNre, *pNim;
    cudaGetSymbolAddress((void**)&pEA,  g_eA);
    cudaGetSymbolAddress((void**)&pEB,  g_eB);
    cudaGetSymbolAddress((void**)&pWT,  g_WT);
    cudaGetSymbolAddress((void**)&pCm,  g_cm);
    cudaGetSymbolAddress((void**)&pCr,  g_cr);
    cudaGetSymbolAddress((void**)&pCi,  g_ci);
    cudaGetSymbolAddress((void**)&pVre, g_vre);
    cudaGetSymbolAddress((void**)&pVim, g_vim);
    cudaGetSymbolAddress((void**)&pOre, g_ore);
    cudaGetSymbolAddress((void**)&pOim, g_oim);
    cudaGetSymbolAddress((void**)&pZ,   g_z);
    cudaGetSymbolAddress((void**)&pRr,  g_rr);
    cudaGetSymbolAddress((void**)&pNre, g_nre);
    cudaGetSymbolAddress((void**)&pNim, g_nim);

    const int SM128 = 2 * (16384 + 16384);          // MROWS=1: 64KB
    const int SM256 = 2 * (32768 + 16384);          // MROWS=2: 96KB
    cudaFuncSetAttribute((const void*)gemm_mma<0, 1>, cudaFuncAttributeMaxDynamicSharedMemorySize, SM128);
    cudaFuncSetAttribute((const void*)gemm_mma<1, 2>, cudaFuncAttributeMaxDynamicSharedMemorySize, SM256);
    cudaFuncSetAttribute((const void*)gemm_mma<2, 2>, cudaFuncAttributeMaxDynamicSharedMemorySize, SM256);

    const size_t EB = (size_t)DO * KENG;
    const size_t WB = (size_t)DH * LDT;

    // streams + events created ONCE (first = correctness call, before the
    // harness's pre-capture memory baseline). Reused every call.
    static cudaStream_t sB = nullptr, sC = nullptr;
    static cudaEvent_t eFork = nullptr, eTe, eTw, ePv, eEng, eC;
    if (sB == nullptr) {
        cudaStreamCreateWithFlags(&sB, cudaStreamNonBlocking);
        cudaStreamCreateWithFlags(&sC, cudaStreamNonBlocking);
        cudaEventCreateWithFlags(&eFork, cudaEventDisableTiming);
        cudaEventCreateWithFlags(&eTe,   cudaEventDisableTiming);
        cudaEventCreateWithFlags(&eTw,   cudaEventDisableTiming);
        cudaEventCreateWithFlags(&ePv,   cudaEventDisableTiming);
        cudaEventCreateWithFlags(&eEng,  cudaEventDisableTiming);
        cudaEventCreateWithFlags(&eC,    cudaEventDisableTiming);
    }

    cudaEventRecord(eFork, 0);
    cudaStreamWaitEvent(sB, eFork, 0);
    cudaStreamWaitEvent(sC, eFork, 0);

    // stream B: engine weight transpose, then GRU weight transpose
    transpose_e<<<dim3(64, 16), dim3(32, 8), 0, sB>>>(ea_wr, ea_wi, eg_wr, eg_wi);
    cudaEventRecord(eTe, sB);
    transpose_w<<<dim3(LDT / 32, 32, 4), dim3(32, 8), 0, sB>>>(gz_w, gr_w, ghr_w, ghi_w);
    cudaEventRecord(eTw, sB);

    // stream C: bias vector
    cudaMemsetAsync(pVre, 0, DO * sizeof(float), sC);
    cudaMemsetAsync(pVim, 0, DO * sizeof(float), sC);
    prep_vec<<<dim3(16, 16), dim3(32, 8), 0, sC>>>(x, ea_wr, ea_br, ea_wi, ea_bi, eg_wr, eg_br, eg_wi, eg_bi);
    cudaEventRecord(ePv, sC);

    // main: activations (also zeroes g_t/g_fmA, writes cm h-mag columns)
    prep_eA<<<2048, 256>>>(h_re, h_im);
    cudaStreamWaitEvent(0, eTe, 0);
    cudaStreamWaitEvent(0, ePv, 0);

    // engine re/im fused (MT=128); epilogue accumulates tension into g_t
    gemm_mma<0, 1><<<dim3(4, 16, 2), 512, SM128>>>(
        pEA, pEA, pEB, pEB + EB,
        KENG, KENG, KENG,
        pOre, pOim, 512,
        pVre, pVim, nullptr, nullptr, nullptr);
    cudaEventRecord(eEng, 0);

    // stream C: softmax stats + weighted sum + final projection
    cudaStreamWaitEvent(sC, eEng, 0);
    stats_k<<<1, 1024, 0, sC>>>(out);
    wsum_k<<<64, 256, 0, sC>>>();
    pred_k<<<512, 256, 0, sC>>>(oh_w, oh_b, out);
    cudaEventRecord(eC, sC);

    // main: GRU chain (MT=256 tiles -> single wave of 128 CTAs)
    build_cm<<<NC, 256>>>(h_re, h_im);
    cudaStreamWaitEvent(0, eTw, 0);
    gemm_mma<1, 2><<<dim3(8, 8, 2), 512, SM256>>>(
        pCm, pCm, pWT + 0 * WB, pWT + 1 * WB,
        LDT, LDT, LDT,
        pZ, pRr, 1024,
        gz_b, gr_b, nullptr, nullptr, nullptr);

    build_comb<<<NC, 256>>>(h_re, h_im);
    gemm_mma<2, 2><<<dim3(8, 8, 2), 512, SM256>>>(
        pCr, pCi, pWT + 2 * WB, pWT + 3 * WB,
        LDT, LDT, LDT,
        pNre, pNim, 1024,
        ghr_b, ghi_b, pZ, h_re, h_im);

    fmean2_k<<<2, 1024>>>();
    apply_sync<<<16384, 256>>>(out, step);

    // join stream C
    cudaStreamWaitEvent(0, eC, 0);
}